// round 1
// baseline (speedup 1.0000x reference)
#include <cuda_runtime.h>
#include <cuda_bf16.h>
#include <math.h>

// ---------------------------------------------------------------------------
// AttentionDisaggregated: prefill (causal self-attn over S=2048) + 1-token decode
// B=2, S=2048, D_MODEL=2048, N_HEADS=16, HEAD_DIM=128
// Inputs (metadata order): x[2,2048,2048] f32, x_new[2,1,2048] f32,
//   wq/wk/wv/wo [2048,16,128] f32 (flat [2048,2048], col = n*128+h)
// Output: prefill_out [2,2048,2048] then decode_out [2,1,2048], flat f32.
// ---------------------------------------------------------------------------

#define D_MODEL 2048
#define SEQ     2048
#define BATCH   2
#define NHEADS  16
#define HDIM    128
#define MROWS   (BATCH * SEQ)          // 4096
#define PREFILL_ELEMS (BATCH * SEQ * D_MODEL)  // 8388608

// Scratch (device globals -- allocation-free rule)
__device__ float g_Q[MROWS * D_MODEL];
__device__ float g_K[MROWS * D_MODEL];
__device__ float g_V[MROWS * D_MODEL];
__device__ float g_A[MROWS * D_MODEL];   // attention output (pre out-proj)
__device__ float g_q1[BATCH * D_MODEL];
__device__ float g_k1[BATCH * D_MODEL];
__device__ float g_v1[BATCH * D_MODEL];
__device__ float g_a1[BATCH * D_MODEL];

// ---------------------------------------------------------------------------
// SGEMM: C[M,N] = A[M,K] @ B[K,N]  (TRANS_B=false)  or  A[M,K] @ B[N,K]^T (true)
// BM=BN=128, BK=8, 256 threads, 8x8 per thread. M%128==0, N%128==0, K%8==0.
// ---------------------------------------------------------------------------
template <bool TRANS_B>
__global__ __launch_bounds__(256) void sgemm_kernel(
    const float* __restrict__ A, const float* __restrict__ B,
    float* __restrict__ C, int M, int N, int K)
{
    __shared__ float As[8][128];
    __shared__ float Bs[8][128];

    const int tid = threadIdx.x;
    const int bm = blockIdx.y * 128;
    const int bn = blockIdx.x * 128;

    // A tile load: 128 rows x 8 k, one float4 per thread, stored transposed
    const int arow = tid >> 1;          // 0..127
    const int acol = (tid & 1) * 4;     // 0 or 4
    // B tile load (NN): 8 k-rows x 128 cols
    const int brow = tid >> 5;          // 0..7
    const int bcol = (tid & 31) * 4;    // 0..124

    const int tx = tid & 15;            // col group
    const int ty = tid >> 4;            // row group

    float acc[8][8];
    #pragma unroll
    for (int i = 0; i < 8; i++)
        #pragma unroll
        for (int j = 0; j < 8; j++) acc[i][j] = 0.f;

    for (int k0 = 0; k0 < K; k0 += 8) {
        float4 av = *reinterpret_cast<const float4*>(&A[(size_t)(bm + arow) * K + k0 + acol]);
        As[acol + 0][arow] = av.x;
        As[acol + 1][arow] = av.y;
        As[acol + 2][arow] = av.z;
        As[acol + 3][arow] = av.w;
        if (TRANS_B) {
            // Bs[k][n] = B[bn+n, k0+k]
            float4 bv = *reinterpret_cast<const float4*>(&B[(size_t)(bn + arow) * K + k0 + acol]);
            Bs[acol + 0][arow] = bv.x;
            Bs[acol + 1][arow] = bv.y;
            Bs[acol + 2][arow] = bv.z;
            Bs[acol + 3][arow] = bv.w;
        } else {
            float4 bv = *reinterpret_cast<const float4*>(&B[(size_t)(k0 + brow) * N + bn + bcol]);
            *reinterpret_cast<float4*>(&Bs[brow][bcol]) = bv;
        }
        __syncthreads();

        #pragma unroll
        for (int kk = 0; kk < 8; kk++) {
            float ar[8], br[8];
            #pragma unroll
            for (int i = 0; i < 8; i++) ar[i] = As[kk][ty * 8 + i];
            #pragma unroll
            for (int j = 0; j < 8; j++) br[j] = Bs[kk][tx * 8 + j];
            #pragma unroll
            for (int i = 0; i < 8; i++)
                #pragma unroll
                for (int j = 0; j < 8; j++) acc[i][j] += ar[i] * br[j];
        }
        __syncthreads();
    }

    #pragma unroll
    for (int i = 0; i < 8; i++) {
        float* crow = &C[(size_t)(bm + ty * 8 + i) * N + bn + tx * 8];
        float4 v0 = make_float4(acc[i][0], acc[i][1], acc[i][2], acc[i][3]);
        float4 v1 = make_float4(acc[i][4], acc[i][5], acc[i][6], acc[i][7]);
        *reinterpret_cast<float4*>(crow + 0) = v0;
        *reinterpret_cast<float4*>(crow + 4) = v1;
    }
}

// ---------------------------------------------------------------------------
// Flash attention prefill (fp32, causal). BQ=BK=32, 128 threads.
// grid = (S/32, NHEADS, BATCH). Reads g_Q/g_K/g_V, writes g_A.
// ---------------------------------------------------------------------------
__global__ __launch_bounds__(128) void flash_prefill_kernel()
{
    const int qi = blockIdx.x;
    const int n  = blockIdx.y;
    const int b  = blockIdx.z;
    const int tid = threadIdx.x;

    __shared__ float Qs[32][129];
    __shared__ float KVs[32][129];
    __shared__ float Ps[32][33];
    __shared__ float m_s[32], l_s[32], alpha_s[32];

    const int m0 = qi * 32;
    const float scale = 0.08838834764831843f;  // 1/sqrt(128)

    const float* Qbase = g_Q + ((size_t)(b * SEQ + m0)) * D_MODEL + n * HDIM;
    for (int i = tid; i < 32 * 128; i += 128) {
        int r = i >> 7, d = i & 127;
        Qs[r][d] = Qbase[(size_t)r * D_MODEL + d];
    }
    if (tid < 32) { m_s[tid] = -INFINITY; l_s[tid] = 0.f; }

    float o[32];
    #pragma unroll
    for (int c = 0; c < 32; c++) o[c] = 0.f;

    const int r_own = tid >> 2;        // O row owned by this thread
    const int cb    = tid & 3;         // O col phase: cols cb + 4*c (conflict-free)
    const int sr0   = (tid >> 4) * 4;  // S rows
    const int sc0   = (tid & 15) * 2;  // S cols
    __syncthreads();

    for (int kt = 0; kt <= qi; kt++) {
        // load K tile
        const float* Kbase = g_K + ((size_t)(b * SEQ + kt * 32)) * D_MODEL + n * HDIM;
        for (int i = tid; i < 32 * 128; i += 128) {
            int r = i >> 7, d = i & 127;
            KVs[r][d] = Kbase[(size_t)r * D_MODEL + d];
        }
        __syncthreads();

        // S = Q K^T (4x2 per thread)
        float sacc[4][2] = {{0.f,0.f},{0.f,0.f},{0.f,0.f},{0.f,0.f}};
        #pragma unroll 4
        for (int d = 0; d < 128; d++) {
            float kv0 = KVs[sc0][d];
            float kv1 = KVs[sc0 + 1][d];
            #pragma unroll
            for (int i = 0; i < 4; i++) {
                float qv = Qs[sr0 + i][d];
                sacc[i][0] += qv * kv0;
                sacc[i][1] += qv * kv1;
            }
        }
        __syncthreads();  // done with K in KVs

        #pragma unroll
        for (int i = 0; i < 4; i++)
            #pragma unroll
            for (int j = 0; j < 2; j++) {
                float s = sacc[i][j] * scale;
                if (kt == qi && (sc0 + j) > (sr0 + i)) s = -INFINITY;
                Ps[sr0 + i][sc0 + j] = s;
            }

        // load V tile into KVs
        const float* Vbase = g_V + ((size_t)(b * SEQ + kt * 32)) * D_MODEL + n * HDIM;
        for (int i = tid; i < 32 * 128; i += 128) {
            int r = i >> 7, d = i & 127;
            KVs[r][d] = Vbase[(size_t)r * D_MODEL + d];
        }
        __syncthreads();

        // online softmax per row (32 threads)
        if (tid < 32) {
            float mold = m_s[tid];
            float mx = mold;
            #pragma unroll
            for (int c = 0; c < 32; c++) mx = fmaxf(mx, Ps[tid][c]);
            float al = __expf(mold - mx);
            float sum = 0.f;
            #pragma unroll
            for (int c = 0; c < 32; c++) {
                float p = __expf(Ps[tid][c] - mx);
                Ps[tid][c] = p;
                sum += p;
            }
            l_s[tid] = l_s[tid] * al + sum;
            m_s[tid] = mx;
            alpha_s[tid] = al;
        }
        __syncthreads();

        // O = O*alpha + P @ V
        float al = alpha_s[r_own];
        #pragma unroll
        for (int c = 0; c < 32; c++) o[c] *= al;
        #pragma unroll 8
        for (int j = 0; j < 32; j++) {
            float p = Ps[r_own][j];
            #pragma unroll
            for (int c = 0; c < 32; c++) o[c] += p * KVs[j][cb + 4 * c];
        }
        __syncthreads();
    }

    float inv = 1.f / l_s[r_own];
    float* Abase = g_A + ((size_t)(b * SEQ + m0 + r_own)) * D_MODEL + n * HDIM;
    #pragma unroll
    for (int c = 0; c < 32; c++) Abase[cb + 4 * c] = o[c] * inv;
}

// ---------------------------------------------------------------------------
// Decode projections: q1/k1/v1[b, col] = sum_d x_new[b,d] * w[d, col]
// grid = (D_MODEL/128, BATCH, 3), block = 128
// ---------------------------------------------------------------------------
__global__ __launch_bounds__(128) void decode_proj_kernel(
    const float* __restrict__ xnew,
    const float* __restrict__ wq, const float* __restrict__ wk,
    const float* __restrict__ wv)
{
    const int col = blockIdx.x * 128 + threadIdx.x;
    const int b = blockIdx.y;
    const int w = blockIdx.z;
    const float* wsel = (w == 0) ? wq : (w == 1) ? wk : wv;
    float* osel = (w == 0) ? g_q1 : (w == 1) ? g_k1 : g_v1;

    __shared__ float xs[D_MODEL];
    for (int i = threadIdx.x; i < D_MODEL; i += 128) xs[i] = xnew[b * D_MODEL + i];
    __syncthreads();

    float acc = 0.f;
    #pragma unroll 8
    for (int d = 0; d < D_MODEL; d++) acc += xs[d] * wsel[(size_t)d * D_MODEL + col];
    osel[b * D_MODEL + col] = acc;
}

// ---------------------------------------------------------------------------
// Decode attention: per (head, batch), softmax over S+1 = 2049 keys.
// grid = (NHEADS, BATCH), block = 128.
// ---------------------------------------------------------------------------
__global__ __launch_bounds__(128) void decode_attn_kernel()
{
    const int n = blockIdx.x;
    const int b = blockIdx.y;
    const int tid = threadIdx.x;

    __shared__ float qs[HDIM];
    __shared__ float sc[SEQ + 1];
    __shared__ float red[128];

    qs[tid] = g_q1[b * D_MODEL + n * HDIM + tid];
    __syncthreads();

    const float scale = 0.08838834764831843f;
    for (int t = tid; t < SEQ + 1; t += 128) {
        const float* kr = (t < SEQ)
            ? (g_K + ((size_t)(b * SEQ + t)) * D_MODEL + n * HDIM)
            : (g_k1 + b * D_MODEL + n * HDIM);
        float s = 0.f;
        #pragma unroll 8
        for (int h = 0; h < HDIM; h++) s += qs[h] * kr[h];
        sc[t] = s * scale;
    }
    __syncthreads();

    // block max
    float mx = -INFINITY;
    for (int t = tid; t < SEQ + 1; t += 128) mx = fmaxf(mx, sc[t]);
    red[tid] = mx;
    __syncthreads();
    for (int s = 64; s > 0; s >>= 1) {
        if (tid < s) red[tid] = fmaxf(red[tid], red[tid + s]);
        __syncthreads();
    }
    mx = red[0];
    __syncthreads();

    // exp + sum
    float sum = 0.f;
    for (int t = tid; t < SEQ + 1; t += 128) {
        float p = __expf(sc[t] - mx);
        sc[t] = p;
        sum += p;
    }
    red[tid] = sum;
    __syncthreads();
    for (int s = 64; s > 0; s >>= 1) {
        if (tid < s) red[tid] += red[tid + s];
        __syncthreads();
    }
    const float inv = 1.f / red[0];
    __syncthreads();

    // out: thread == h channel
    float acc = 0.f;
    #pragma unroll 4
    for (int t = 0; t < SEQ; t++)
        acc += sc[t] * g_V[((size_t)(b * SEQ + t)) * D_MODEL + n * HDIM + tid];
    acc += sc[SEQ] * g_v1[b * D_MODEL + n * HDIM + tid];
    g_a1[b * D_MODEL + n * HDIM + tid] = acc * inv;
}

// ---------------------------------------------------------------------------
// Decode output projection: out[b,d] = sum_k g_a1[b,k] * wo[d,k]
// one warp per output. grid = 512 blocks x 256 threads.
// ---------------------------------------------------------------------------
__global__ __launch_bounds__(256) void decode_out_kernel(
    const float* __restrict__ wo, float* __restrict__ out)
{
    const int gw = (blockIdx.x * 256 + threadIdx.x) >> 5;
    const int lane = threadIdx.x & 31;
    if (gw >= BATCH * D_MODEL) return;
    const int b = gw >> 11;
    const int d = gw & (D_MODEL - 1);

    const float* a = g_a1 + b * D_MODEL;
    const float* w = wo + (size_t)d * D_MODEL;
    float acc = 0.f;
    for (int k = lane * 4; k < D_MODEL; k += 128) {
        float4 av = *reinterpret_cast<const float4*>(a + k);
        float4 wv = *reinterpret_cast<const float4*>(w + k);
        acc += av.x * wv.x + av.y * wv.y + av.z * wv.z + av.w * wv.w;
    }
    #pragma unroll
    for (int o = 16; o > 0; o >>= 1) acc += __shfl_down_sync(0xffffffff, acc, o);
    if (lane == 0) out[PREFILL_ELEMS + b * D_MODEL + d] = acc;
}

// ---------------------------------------------------------------------------
extern "C" void kernel_launch(void* const* d_in, const int* in_sizes, int n_in,
                              void* d_out, int out_size)
{
    const float* x     = (const float*)d_in[0];
    const float* x_new = (const float*)d_in[1];
    const float* wq    = (const float*)d_in[2];
    const float* wk    = (const float*)d_in[3];
    const float* wv    = (const float*)d_in[4];
    const float* wo    = (const float*)d_in[5];
    float* out = (float*)d_out;

    float *pQ, *pK, *pV, *pA;
    cudaGetSymbolAddress((void**)&pQ, g_Q);
    cudaGetSymbolAddress((void**)&pK, g_K);
    cudaGetSymbolAddress((void**)&pV, g_V);
    cudaGetSymbolAddress((void**)&pA, g_A);

    dim3 ggrid(D_MODEL / 128, MROWS / 128);  // (16, 32)

    // Q/K/V projections
    sgemm_kernel<false><<<ggrid, 256>>>(x, wq, pQ, MROWS, D_MODEL, D_MODEL);
    sgemm_kernel<false><<<ggrid, 256>>>(x, wk, pK, MROWS, D_MODEL, D_MODEL);
    sgemm_kernel<false><<<ggrid, 256>>>(x, wv, pV, MROWS, D_MODEL, D_MODEL);

    // Prefill flash attention
    dim3 fgrid(SEQ / 32, NHEADS, BATCH);
    flash_prefill_kernel<<<fgrid, 128>>>();

    // Output projection (B transposed): prefill_out = A @ wo^T
    sgemm_kernel<true><<<ggrid, 256>>>(pA, wo, out, MROWS, D_MODEL, D_MODEL);

    // Decode path
    dim3 dpgrid(D_MODEL / 128, BATCH, 3);
    decode_proj_kernel<<<dpgrid, 128>>>(x_new, wq, wk, wv);
    dim3 dagrid(NHEADS, BATCH);
    decode_attn_kernel<<<dagrid, 128>>>();
    decode_out_kernel<<<512, 256>>>(wo, out);
}

// round 2
// speedup vs baseline: 2.5483x; 2.5483x over previous
#include <cuda_runtime.h>
#include <cuda_bf16.h>
#include <math.h>

// ---------------------------------------------------------------------------
// AttentionDisaggregated: prefill (causal self-attn over S=2048) + 1-token decode
// B=2, S=2048, D_MODEL=2048, N_HEADS=16, HEAD_DIM=128
// Round 2: projection GEMMs moved to tf32 tensor cores (mma.sync m16n8k8).
// ---------------------------------------------------------------------------

#define D_MODEL 2048
#define SEQ     2048
#define BATCH   2
#define NHEADS  16
#define HDIM    128
#define MROWS   (BATCH * SEQ)          // 4096
#define PREFILL_ELEMS (BATCH * SEQ * D_MODEL)  // 8388608

// Scratch (device globals -- allocation-free rule)
__device__ float g_Q[MROWS * D_MODEL];
__device__ float g_K[MROWS * D_MODEL];
__device__ float g_V[MROWS * D_MODEL];
__device__ float g_A[MROWS * D_MODEL];   // attention output (pre out-proj)
__device__ float g_q1[BATCH * D_MODEL];
__device__ float g_k1[BATCH * D_MODEL];
__device__ float g_v1[BATCH * D_MODEL];
__device__ float g_a1[BATCH * D_MODEL];

// ---------------------------------------------------------------------------
// tf32 helpers
// ---------------------------------------------------------------------------
__device__ __forceinline__ float to_tf32(float x) {
    unsigned u;
    asm("cvt.rna.tf32.f32 %0, %1;" : "=r"(u) : "f"(x));
    return __uint_as_float(u);
}

__device__ __forceinline__ void mma_tf32(float* c, const unsigned* a, const unsigned* b) {
    asm volatile(
        "mma.sync.aligned.m16n8k8.row.col.f32.tf32.tf32.f32 "
        "{%0,%1,%2,%3}, {%4,%5,%6,%7}, {%8,%9}, {%0,%1,%2,%3};\n"
        : "+f"(c[0]), "+f"(c[1]), "+f"(c[2]), "+f"(c[3])
        : "r"(a[0]), "r"(a[1]), "r"(a[2]), "r"(a[3]), "r"(b[0]), "r"(b[1]));
}

// ---------------------------------------------------------------------------
// Tensor-core GEMM (tf32): C[M,N] = A[M,K] @ B[K,N]   (TRANS_B=false)
//                       or C[M,N] = A[M,K] @ B[N,K]^T (TRANS_B=true)
// BM=BN=128, BK=16, 256 threads, 8 warps each 32x64. Double-buffered smem.
// blockIdx.z selects among up to 3 (B, C) pairs (fused QKV).
// M%128==0, N%128==0, K%16==0.
// ---------------------------------------------------------------------------
template <bool TRANS_B>
__global__ __launch_bounds__(256) void mma_gemm_kernel(
    const float* __restrict__ A,
    const float* __restrict__ B0, const float* __restrict__ B1, const float* __restrict__ B2,
    float* __restrict__ C0, float* __restrict__ C1, float* __restrict__ C2,
    int M, int N, int K)
{
    const float* Bg = (blockIdx.z == 0) ? B0 : (blockIdx.z == 1) ? B1 : B2;
    float*       Cg = (blockIdx.z == 0) ? C0 : (blockIdx.z == 1) ? C1 : C2;

    // As: [m][k] padded to 20 -> conflict-free frag loads + coalesced float4 STS
    // Bs NN: [k][n] padded to 136 ; Bs NT: [n][k] padded to 20
    __shared__ float As[2][128][20];
    __shared__ float Bs[2][2560];

    const int tid  = threadIdx.x;
    const int bm   = blockIdx.y * 128;
    const int bn   = blockIdx.x * 128;
    const int lane = tid & 31;
    const int warp = tid >> 5;
    const int wm   = (warp >> 1) * 32;   // warp row origin
    const int wn   = (warp & 1) * 64;    // warp col origin
    const int fr   = lane >> 2;          // fragment row / n index (0..7)
    const int fc   = lane & 3;           // fragment k index (0..3)

    // global load mapping
    const int a_r = tid >> 2;            // 0..63 (+64)
    const int a_c = (tid & 3) * 4;       // 0,4,8,12
    const int b_k = tid >> 4;            // 0..15   (NN)
    const int b_n = (tid & 15) * 8;      // 0..120  (NN)

    float acc[2][8][4];
    #pragma unroll
    for (int i = 0; i < 2; i++)
        #pragma unroll
        for (int j = 0; j < 8; j++)
            #pragma unroll
            for (int q = 0; q < 4; q++) acc[i][j][q] = 0.f;

    float4 ra[2], rb[2];

    auto issue_loads = [&](int k0) {
        #pragma unroll
        for (int h = 0; h < 2; h++)
            ra[h] = *reinterpret_cast<const float4*>(&A[(size_t)(bm + a_r + 64 * h) * K + k0 + a_c]);
        if (TRANS_B) {
            #pragma unroll
            for (int h = 0; h < 2; h++)
                rb[h] = *reinterpret_cast<const float4*>(&Bg[(size_t)(bn + a_r + 64 * h) * K + k0 + a_c]);
        } else {
            rb[0] = *reinterpret_cast<const float4*>(&Bg[(size_t)(k0 + b_k) * N + bn + b_n]);
            rb[1] = *reinterpret_cast<const float4*>(&Bg[(size_t)(k0 + b_k) * N + bn + b_n + 4]);
        }
    };

    auto store_tiles = [&](int sb) {
        #pragma unroll
        for (int h = 0; h < 2; h++) {
            float* p = &As[sb][a_r + 64 * h][a_c];
            p[0] = to_tf32(ra[h].x); p[1] = to_tf32(ra[h].y);
            p[2] = to_tf32(ra[h].z); p[3] = to_tf32(ra[h].w);
        }
        if (TRANS_B) {
            #pragma unroll
            for (int h = 0; h < 2; h++) {
                float* p = &Bs[sb][(a_r + 64 * h) * 20 + a_c];
                p[0] = to_tf32(rb[h].x); p[1] = to_tf32(rb[h].y);
                p[2] = to_tf32(rb[h].z); p[3] = to_tf32(rb[h].w);
            }
        } else {
            float* p = &Bs[sb][b_k * 136 + b_n];
            p[0] = to_tf32(rb[0].x); p[1] = to_tf32(rb[0].y);
            p[2] = to_tf32(rb[0].z); p[3] = to_tf32(rb[0].w);
            p[4] = to_tf32(rb[1].x); p[5] = to_tf32(rb[1].y);
            p[6] = to_tf32(rb[1].z); p[7] = to_tf32(rb[1].w);
        }
    };

    issue_loads(0);
    store_tiles(0);
    __syncthreads();

    int buf = 0;
    for (int k0 = 0; k0 < K; k0 += 16) {
        const bool has_next = (k0 + 16) < K;
        if (has_next) issue_loads(k0 + 16);   // LDG in flight during compute

        #pragma unroll
        for (int kk = 0; kk < 16; kk += 8) {
            unsigned afr[2][4];
            #pragma unroll
            for (int mt = 0; mt < 2; mt++) {
                const int m0 = wm + mt * 16;
                afr[mt][0] = __float_as_uint(As[buf][m0 + fr    ][kk + fc]);
                afr[mt][1] = __float_as_uint(As[buf][m0 + fr + 8][kk + fc]);
                afr[mt][2] = __float_as_uint(As[buf][m0 + fr    ][kk + fc + 4]);
                afr[mt][3] = __float_as_uint(As[buf][m0 + fr + 8][kk + fc + 4]);
            }
            #pragma unroll
            for (int nt = 0; nt < 8; nt++) {
                unsigned bfr[2];
                const int n0 = wn + nt * 8 + fr;
                if (TRANS_B) {
                    bfr[0] = __float_as_uint(Bs[buf][n0 * 20 + kk + fc]);
                    bfr[1] = __float_as_uint(Bs[buf][n0 * 20 + kk + fc + 4]);
                } else {
                    bfr[0] = __float_as_uint(Bs[buf][(kk + fc)     * 136 + n0]);
                    bfr[1] = __float_as_uint(Bs[buf][(kk + fc + 4) * 136 + n0]);
                }
                mma_tf32(acc[0][nt], afr[0], bfr);
                mma_tf32(acc[1][nt], afr[1], bfr);
            }
        }

        if (has_next) store_tiles(buf ^ 1);
        __syncthreads();
        buf ^= 1;
    }

    #pragma unroll
    for (int mt = 0; mt < 2; mt++) {
        #pragma unroll
        for (int nt = 0; nt < 8; nt++) {
            const int row0 = bm + wm + mt * 16 + fr;
            const int col  = bn + wn + nt * 8 + 2 * fc;
            *reinterpret_cast<float2*>(&Cg[(size_t)row0 * N + col]) =
                make_float2(acc[mt][nt][0], acc[mt][nt][1]);
            *reinterpret_cast<float2*>(&Cg[(size_t)(row0 + 8) * N + col]) =
                make_float2(acc[mt][nt][2], acc[mt][nt][3]);
        }
    }
}

// ---------------------------------------------------------------------------
// Flash attention prefill (fp32, causal). BQ=BK=32, 128 threads.
// grid = (S/32, NHEADS, BATCH). Reads g_Q/g_K/g_V, writes g_A.
// ---------------------------------------------------------------------------
__global__ __launch_bounds__(128) void flash_prefill_kernel()
{
    const int qi = blockIdx.x;
    const int n  = blockIdx.y;
    const int b  = blockIdx.z;
    const int tid = threadIdx.x;

    __shared__ float Qs[32][129];
    __shared__ float KVs[32][129];
    __shared__ float Ps[32][33];
    __shared__ float m_s[32], l_s[32], alpha_s[32];

    const int m0 = qi * 32;
    const float scale = 0.08838834764831843f;  // 1/sqrt(128)

    const float* Qbase = g_Q + ((size_t)(b * SEQ + m0)) * D_MODEL + n * HDIM;
    for (int i = tid; i < 32 * 128; i += 128) {
        int r = i >> 7, d = i & 127;
        Qs[r][d] = Qbase[(size_t)r * D_MODEL + d];
    }
    if (tid < 32) { m_s[tid] = -INFINITY; l_s[tid] = 0.f; }

    float o[32];
    #pragma unroll
    for (int c = 0; c < 32; c++) o[c] = 0.f;

    const int r_own = tid >> 2;        // O row owned by this thread
    const int cb    = tid & 3;         // O col phase: cols cb + 4*c (conflict-free)
    const int sr0   = (tid >> 4) * 4;  // S rows
    const int sc0   = (tid & 15) * 2;  // S cols
    __syncthreads();

    for (int kt = 0; kt <= qi; kt++) {
        // load K tile
        const float* Kbase = g_K + ((size_t)(b * SEQ + kt * 32)) * D_MODEL + n * HDIM;
        for (int i = tid; i < 32 * 128; i += 128) {
            int r = i >> 7, d = i & 127;
            KVs[r][d] = Kbase[(size_t)r * D_MODEL + d];
        }
        __syncthreads();

        // S = Q K^T (4x2 per thread)
        float sacc[4][2] = {{0.f,0.f},{0.f,0.f},{0.f,0.f},{0.f,0.f}};
        #pragma unroll 4
        for (int d = 0; d < 128; d++) {
            float kv0 = KVs[sc0][d];
            float kv1 = KVs[sc0 + 1][d];
            #pragma unroll
            for (int i = 0; i < 4; i++) {
                float qv = Qs[sr0 + i][d];
                sacc[i][0] += qv * kv0;
                sacc[i][1] += qv * kv1;
            }
        }
        __syncthreads();  // done with K in KVs

        #pragma unroll
        for (int i = 0; i < 4; i++)
            #pragma unroll
            for (int j = 0; j < 2; j++) {
                float s = sacc[i][j] * scale;
                if (kt == qi && (sc0 + j) > (sr0 + i)) s = -INFINITY;
                Ps[sr0 + i][sc0 + j] = s;
            }

        // load V tile into KVs
        const float* Vbase = g_V + ((size_t)(b * SEQ + kt * 32)) * D_MODEL + n * HDIM;
        for (int i = tid; i < 32 * 128; i += 128) {
            int r = i >> 7, d = i & 127;
            KVs[r][d] = Vbase[(size_t)r * D_MODEL + d];
        }
        __syncthreads();

        // online softmax per row (32 threads)
        if (tid < 32) {
            float mold = m_s[tid];
            float mx = mold;
            #pragma unroll
            for (int c = 0; c < 32; c++) mx = fmaxf(mx, Ps[tid][c]);
            float al = __expf(mold - mx);
            float sum = 0.f;
            #pragma unroll
            for (int c = 0; c < 32; c++) {
                float p = __expf(Ps[tid][c] - mx);
                Ps[tid][c] = p;
                sum += p;
            }
            l_s[tid] = l_s[tid] * al + sum;
            m_s[tid] = mx;
            alpha_s[tid] = al;
        }
        __syncthreads();

        // O = O*alpha + P @ V
        float al = alpha_s[r_own];
        #pragma unroll
        for (int c = 0; c < 32; c++) o[c] *= al;
        #pragma unroll 8
        for (int j = 0; j < 32; j++) {
            float p = Ps[r_own][j];
            #pragma unroll
            for (int c = 0; c < 32; c++) o[c] += p * KVs[j][cb + 4 * c];
        }
        __syncthreads();
    }

    float inv = 1.f / l_s[r_own];
    float* Abase = g_A + ((size_t)(b * SEQ + m0 + r_own)) * D_MODEL + n * HDIM;
    #pragma unroll
    for (int c = 0; c < 32; c++) Abase[cb + 4 * c] = o[c] * inv;
}

// ---------------------------------------------------------------------------
// Decode projections: q1/k1/v1[b, col] = sum_d x_new[b,d] * w[d, col]
// grid = (D_MODEL/128, BATCH, 3), block = 128
// ---------------------------------------------------------------------------
__global__ __launch_bounds__(128) void decode_proj_kernel(
    const float* __restrict__ xnew,
    const float* __restrict__ wq, const float* __restrict__ wk,
    const float* __restrict__ wv)
{
    const int col = blockIdx.x * 128 + threadIdx.x;
    const int b = blockIdx.y;
    const int w = blockIdx.z;
    const float* wsel = (w == 0) ? wq : (w == 1) ? wk : wv;
    float* osel = (w == 0) ? g_q1 : (w == 1) ? g_k1 : g_v1;

    __shared__ float xs[D_MODEL];
    for (int i = threadIdx.x; i < D_MODEL; i += 128) xs[i] = xnew[b * D_MODEL + i];
    __syncthreads();

    float acc = 0.f;
    #pragma unroll 8
    for (int d = 0; d < D_MODEL; d++) acc += xs[d] * wsel[(size_t)d * D_MODEL + col];
    osel[b * D_MODEL + col] = acc;
}

// ---------------------------------------------------------------------------
// Decode attention: per (head, batch), softmax over S+1 = 2049 keys.
// grid = (NHEADS, BATCH), block = 128.
// ---------------------------------------------------------------------------
__global__ __launch_bounds__(128) void decode_attn_kernel()
{
    const int n = blockIdx.x;
    const int b = blockIdx.y;
    const int tid = threadIdx.x;

    __shared__ float qs[HDIM];
    __shared__ float sc[SEQ + 1];
    __shared__ float red[128];

    qs[tid] = g_q1[b * D_MODEL + n * HDIM + tid];
    __syncthreads();

    const float scale = 0.08838834764831843f;
    for (int t = tid; t < SEQ + 1; t += 128) {
        const float* kr = (t < SEQ)
            ? (g_K + ((size_t)(b * SEQ + t)) * D_MODEL + n * HDIM)
            : (g_k1 + b * D_MODEL + n * HDIM);
        float s = 0.f;
        #pragma unroll 8
        for (int h = 0; h < HDIM; h++) s += qs[h] * kr[h];
        sc[t] = s * scale;
    }
    __syncthreads();

    // block max
    float mx = -INFINITY;
    for (int t = tid; t < SEQ + 1; t += 128) mx = fmaxf(mx, sc[t]);
    red[tid] = mx;
    __syncthreads();
    for (int s = 64; s > 0; s >>= 1) {
        if (tid < s) red[tid] = fmaxf(red[tid], red[tid + s]);
        __syncthreads();
    }
    mx = red[0];
    __syncthreads();

    // exp + sum
    float sum = 0.f;
    for (int t = tid; t < SEQ + 1; t += 128) {
        float p = __expf(sc[t] - mx);
        sc[t] = p;
        sum += p;
    }
    red[tid] = sum;
    __syncthreads();
    for (int s = 64; s > 0; s >>= 1) {
        if (tid < s) red[tid] += red[tid + s];
        __syncthreads();
    }
    const float inv = 1.f / red[0];
    __syncthreads();

    // out: thread == h channel
    float acc = 0.f;
    #pragma unroll 4
    for (int t = 0; t < SEQ; t++)
        acc += sc[t] * g_V[((size_t)(b * SEQ + t)) * D_MODEL + n * HDIM + tid];
    acc += sc[SEQ] * g_v1[b * D_MODEL + n * HDIM + tid];
    g_a1[b * D_MODEL + n * HDIM + tid] = acc * inv;
}

// ---------------------------------------------------------------------------
// Decode output projection: out[b,d] = sum_k g_a1[b,k] * wo[d,k]
// one warp per output. grid = 512 blocks x 256 threads.
// ---------------------------------------------------------------------------
__global__ __launch_bounds__(256) void decode_out_kernel(
    const float* __restrict__ wo, float* __restrict__ out)
{
    const int gw = (blockIdx.x * 256 + threadIdx.x) >> 5;
    const int lane = threadIdx.x & 31;
    if (gw >= BATCH * D_MODEL) return;
    const int b = gw >> 11;
    const int d = gw & (D_MODEL - 1);

    const float* a = g_a1 + b * D_MODEL;
    const float* w = wo + (size_t)d * D_MODEL;
    float acc = 0.f;
    for (int k = lane * 4; k < D_MODEL; k += 128) {
        float4 av = *reinterpret_cast<const float4*>(a + k);
        float4 wv = *reinterpret_cast<const float4*>(w + k);
        acc += av.x * wv.x + av.y * wv.y + av.z * wv.z + av.w * wv.w;
    }
    #pragma unroll
    for (int o = 16; o > 0; o >>= 1) acc += __shfl_down_sync(0xffffffff, acc, o);
    if (lane == 0) out[PREFILL_ELEMS + b * D_MODEL + d] = acc;
}

// ---------------------------------------------------------------------------
extern "C" void kernel_launch(void* const* d_in, const int* in_sizes, int n_in,
                              void* d_out, int out_size)
{
    const float* x     = (const float*)d_in[0];
    const float* x_new = (const float*)d_in[1];
    const float* wq    = (const float*)d_in[2];
    const float* wk    = (const float*)d_in[3];
    const float* wv    = (const float*)d_in[4];
    const float* wo    = (const float*)d_in[5];
    float* out = (float*)d_out;

    float *pQ, *pK, *pV, *pA;
    cudaGetSymbolAddress((void**)&pQ, g_Q);
    cudaGetSymbolAddress((void**)&pK, g_K);
    cudaGetSymbolAddress((void**)&pV, g_V);
    cudaGetSymbolAddress((void**)&pA, g_A);

    // Fused Q/K/V projections on tensor cores (tf32)
    dim3 g3(D_MODEL / 128, MROWS / 128, 3);  // (16, 32, 3)
    mma_gemm_kernel<false><<<g3, 256>>>(x, wq, wk, wv, pQ, pK, pV,
                                        MROWS, D_MODEL, D_MODEL);

    // Prefill flash attention
    dim3 fgrid(SEQ / 32, NHEADS, BATCH);
    flash_prefill_kernel<<<fgrid, 128>>>();

    // Output projection (B transposed): prefill_out = A @ wo^T
    dim3 g1(D_MODEL / 128, MROWS / 128, 1);
    mma_gemm_kernel<true><<<g1, 256>>>(pA, wo, wo, wo, out, out, out,
                                       MROWS, D_MODEL, D_MODEL);

    // Decode path
    dim3 dpgrid(D_MODEL / 128, BATCH, 3);
    decode_proj_kernel<<<dpgrid, 128>>>(x_new, wq, wk, wv);
    dim3 dagrid(NHEADS, BATCH);
    decode_attn_kernel<<<dagrid, 128>>>();
    decode_out_kernel<<<512, 256>>>(wo, out);
}

// round 3
// speedup vs baseline: 3.9442x; 1.5478x over previous
#include <cuda_runtime.h>
#include <cuda_bf16.h>
#include <math.h>

// ---------------------------------------------------------------------------
// AttentionDisaggregated: prefill (causal self-attn over S=2048) + 1-token decode
// B=2, S=2048, D_MODEL=2048, N_HEADS=16, HEAD_DIM=128
// Round 3: flash prefill on tf32 mma (3-mma hi/lo splits), decode kernels fixed.
// ---------------------------------------------------------------------------

#define D_MODEL 2048
#define SEQ     2048
#define BATCH   2
#define NHEADS  16
#define HDIM    128
#define MROWS   (BATCH * SEQ)          // 4096
#define PREFILL_ELEMS (BATCH * SEQ * D_MODEL)  // 8388608

// Scratch (device globals -- allocation-free rule)
__device__ float g_Q[MROWS * D_MODEL];
__device__ float g_K[MROWS * D_MODEL];
__device__ float g_V[MROWS * D_MODEL];
__device__ float g_A[MROWS * D_MODEL];   // attention output (pre out-proj)
__device__ float g_q1[BATCH * D_MODEL];
__device__ float g_k1[BATCH * D_MODEL];
__device__ float g_v1[BATCH * D_MODEL];
__device__ float g_a1[BATCH * D_MODEL];

// ---------------------------------------------------------------------------
// tf32 helpers
// ---------------------------------------------------------------------------
__device__ __forceinline__ float to_tf32(float x) {
    unsigned u;
    asm("cvt.rna.tf32.f32 %0, %1;" : "=r"(u) : "f"(x));
    return __uint_as_float(u);
}

__device__ __forceinline__ void split_tf32(float x, unsigned& hi, unsigned& lo) {
    asm("cvt.rna.tf32.f32 %0, %1;" : "=r"(hi) : "f"(x));
    float hf = __uint_as_float(hi);
    asm("cvt.rna.tf32.f32 %0, %1;" : "=r"(lo) : "f"(x - hf));
}

__device__ __forceinline__ void mma_tf32(float* c, const unsigned* a, const unsigned* b) {
    asm volatile(
        "mma.sync.aligned.m16n8k8.row.col.f32.tf32.tf32.f32 "
        "{%0,%1,%2,%3}, {%4,%5,%6,%7}, {%8,%9}, {%0,%1,%2,%3};\n"
        : "+f"(c[0]), "+f"(c[1]), "+f"(c[2]), "+f"(c[3])
        : "r"(a[0]), "r"(a[1]), "r"(a[2]), "r"(a[3]), "r"(b[0]), "r"(b[1]));
}

// ---------------------------------------------------------------------------
// Tensor-core GEMM (tf32): C[M,N] = A[M,K] @ B[K,N]   (TRANS_B=false)
//                       or C[M,N] = A[M,K] @ B[N,K]^T (TRANS_B=true)
// BM=BN=128, BK=16, 256 threads, 8 warps each 32x64. Double-buffered smem.
// ---------------------------------------------------------------------------
template <bool TRANS_B>
__global__ __launch_bounds__(256, 2) void mma_gemm_kernel(
    const float* __restrict__ A,
    const float* __restrict__ B0, const float* __restrict__ B1, const float* __restrict__ B2,
    float* __restrict__ C0, float* __restrict__ C1, float* __restrict__ C2,
    int M, int N, int K)
{
    const float* Bg = (blockIdx.z == 0) ? B0 : (blockIdx.z == 1) ? B1 : B2;
    float*       Cg = (blockIdx.z == 0) ? C0 : (blockIdx.z == 1) ? C1 : C2;

    __shared__ float As[2][128][20];
    __shared__ float Bs[2][2560];

    const int tid  = threadIdx.x;
    const int bm   = blockIdx.y * 128;
    const int bn   = blockIdx.x * 128;
    const int lane = tid & 31;
    const int warp = tid >> 5;
    const int wm   = (warp >> 1) * 32;
    const int wn   = (warp & 1) * 64;
    const int fr   = lane >> 2;
    const int fc   = lane & 3;

    const int a_r = tid >> 2;
    const int a_c = (tid & 3) * 4;
    const int b_k = tid >> 4;
    const int b_n = (tid & 15) * 8;

    float acc[2][8][4];
    #pragma unroll
    for (int i = 0; i < 2; i++)
        #pragma unroll
        for (int j = 0; j < 8; j++)
            #pragma unroll
            for (int q = 0; q < 4; q++) acc[i][j][q] = 0.f;

    float4 ra[2], rb[2];

    auto issue_loads = [&](int k0) {
        #pragma unroll
        for (int h = 0; h < 2; h++)
            ra[h] = *reinterpret_cast<const float4*>(&A[(size_t)(bm + a_r + 64 * h) * K + k0 + a_c]);
        if (TRANS_B) {
            #pragma unroll
            for (int h = 0; h < 2; h++)
                rb[h] = *reinterpret_cast<const float4*>(&Bg[(size_t)(bn + a_r + 64 * h) * K + k0 + a_c]);
        } else {
            rb[0] = *reinterpret_cast<const float4*>(&Bg[(size_t)(k0 + b_k) * N + bn + b_n]);
            rb[1] = *reinterpret_cast<const float4*>(&Bg[(size_t)(k0 + b_k) * N + bn + b_n + 4]);
        }
    };

    auto store_tiles = [&](int sb) {
        #pragma unroll
        for (int h = 0; h < 2; h++) {
            float* p = &As[sb][a_r + 64 * h][a_c];
            p[0] = to_tf32(ra[h].x); p[1] = to_tf32(ra[h].y);
            p[2] = to_tf32(ra[h].z); p[3] = to_tf32(ra[h].w);
        }
        if (TRANS_B) {
            #pragma unroll
            for (int h = 0; h < 2; h++) {
                float* p = &Bs[sb][(a_r + 64 * h) * 20 + a_c];
                p[0] = to_tf32(rb[h].x); p[1] = to_tf32(rb[h].y);
                p[2] = to_tf32(rb[h].z); p[3] = to_tf32(rb[h].w);
            }
        } else {
            float* p = &Bs[sb][b_k * 136 + b_n];
            p[0] = to_tf32(rb[0].x); p[1] = to_tf32(rb[0].y);
            p[2] = to_tf32(rb[0].z); p[3] = to_tf32(rb[0].w);
            p[4] = to_tf32(rb[1].x); p[5] = to_tf32(rb[1].y);
            p[6] = to_tf32(rb[1].z); p[7] = to_tf32(rb[1].w);
        }
    };

    issue_loads(0);
    store_tiles(0);
    __syncthreads();

    int buf = 0;
    for (int k0 = 0; k0 < K; k0 += 16) {
        const bool has_next = (k0 + 16) < K;
        if (has_next) issue_loads(k0 + 16);

        #pragma unroll
        for (int kk = 0; kk < 16; kk += 8) {
            unsigned afr[2][4];
            #pragma unroll
            for (int mt = 0; mt < 2; mt++) {
                const int m0 = wm + mt * 16;
                afr[mt][0] = __float_as_uint(As[buf][m0 + fr    ][kk + fc]);
                afr[mt][1] = __float_as_uint(As[buf][m0 + fr + 8][kk + fc]);
                afr[mt][2] = __float_as_uint(As[buf][m0 + fr    ][kk + fc + 4]);
                afr[mt][3] = __float_as_uint(As[buf][m0 + fr + 8][kk + fc + 4]);
            }
            #pragma unroll
            for (int nt = 0; nt < 8; nt++) {
                unsigned bfr[2];
                const int n0 = wn + nt * 8 + fr;
                if (TRANS_B) {
                    bfr[0] = __float_as_uint(Bs[buf][n0 * 20 + kk + fc]);
                    bfr[1] = __float_as_uint(Bs[buf][n0 * 20 + kk + fc + 4]);
                } else {
                    bfr[0] = __float_as_uint(Bs[buf][(kk + fc)     * 136 + n0]);
                    bfr[1] = __float_as_uint(Bs[buf][(kk + fc + 4) * 136 + n0]);
                }
                mma_tf32(acc[0][nt], afr[0], bfr);
                mma_tf32(acc[1][nt], afr[1], bfr);
            }
        }

        if (has_next) store_tiles(buf ^ 1);
        __syncthreads();
        buf ^= 1;
    }

    #pragma unroll
    for (int mt = 0; mt < 2; mt++) {
        #pragma unroll
        for (int nt = 0; nt < 8; nt++) {
            const int row0 = bm + wm + mt * 16 + fr;
            const int col  = bn + wn + nt * 8 + 2 * fc;
            *reinterpret_cast<float2*>(&Cg[(size_t)row0 * N + col]) =
                make_float2(acc[mt][nt][0], acc[mt][nt][1]);
            *reinterpret_cast<float2*>(&Cg[(size_t)(row0 + 8) * N + col]) =
                make_float2(acc[mt][nt][2], acc[mt][nt][3]);
        }
    }
}

// ---------------------------------------------------------------------------
// Flash attention prefill on tf32 mma with hi/lo 3-mma splits (near-fp32).
// BQ=64, BK=64, 256 threads (8 warps). Dynamic smem ~118KB, 1 CTA/SM.
// grid = (SEQ/64, NHEADS, BATCH).
// ---------------------------------------------------------------------------
#define FQP 132   // Q row pad (4 mod 32 -> conflict-free a-frags)
#define FKP 132   // K row pad
#define FVP 136   // V row pad (8 mod 32 -> conflict-free b-frags)
#define FPP 68    // P row pad
#define FQ_OFF 0
#define FK_OFF (64 * FQP)
#define FV_OFF (FK_OFF + 64 * FKP)
#define FP_OFF (FV_OFF + 64 * FVP)
#define FM_OFF (FP_OFF + 64 * FPP)
#define FL_OFF (FM_OFF + 64)
#define FA_OFF (FL_OFF + 64)
#define FLASH_SMEM_FLOATS (FA_OFF + 64)

__global__ __launch_bounds__(256) void flash_mma_kernel()
{
    extern __shared__ float fsm[];
    float* Qs = fsm + FQ_OFF;
    float* Ks = fsm + FK_OFF;
    float* Vs = fsm + FV_OFF;
    float* Ps = fsm + FP_OFF;
    float* m_s = fsm + FM_OFF;
    float* l_s = fsm + FL_OFF;
    float* al_s = fsm + FA_OFF;

    const int qi = blockIdx.x;
    const int n  = blockIdx.y;
    const int b  = blockIdx.z;
    const int tid  = threadIdx.x;
    const int lane = tid & 31;
    const int warp = tid >> 5;
    const int wm   = (warp >> 1) * 16;   // warp row block (4 groups)
    const int wh   = (warp & 1);         // half selector
    const int fr   = lane >> 2;
    const int fc   = lane & 3;

    const float scale = 0.08838834764831843f;  // 1/sqrt(128)

    // global tile load mapping: row = tid&63, col base = (tid>>6)*32, 8 float4s
    const int g_r  = tid & 63;
    const int g_c0 = (tid >> 6) * 32;

    const size_t head_off = (size_t)n * HDIM;
    const float* Qg = g_Q + ((size_t)(b * SEQ + qi * 64)) * D_MODEL + head_off;

    // Load Q (scaled by softmax scale)
    #pragma unroll
    for (int i = 0; i < 8; i++) {
        float4 v = *reinterpret_cast<const float4*>(&Qg[(size_t)g_r * D_MODEL + g_c0 + 4 * i]);
        float* p = &Qs[g_r * FQP + g_c0 + 4 * i];
        p[0] = v.x * scale; p[1] = v.y * scale; p[2] = v.z * scale; p[3] = v.w * scale;
    }
    if (tid < 64) { m_s[tid] = -INFINITY; l_s[tid] = 0.f; }

    // Load K tile 0 directly; prefetch V tile 0 into registers
    const float* Kg0 = g_K + ((size_t)(b * SEQ)) * D_MODEL + head_off;
    const float* Vg0 = g_V + ((size_t)(b * SEQ)) * D_MODEL + head_off;
    #pragma unroll
    for (int i = 0; i < 8; i++) {
        float4 v = *reinterpret_cast<const float4*>(&Kg0[(size_t)g_r * D_MODEL + g_c0 + 4 * i]);
        *reinterpret_cast<float4*>(&Ks[g_r * FKP + g_c0 + 4 * i]) = v;
    }
    float4 vreg[8];
    #pragma unroll
    for (int i = 0; i < 8; i++)
        vreg[i] = *reinterpret_cast<const float4*>(&Vg0[(size_t)g_r * D_MODEL + g_c0 + 4 * i]);
    __syncthreads();

    float o[8][4];
    #pragma unroll
    for (int i = 0; i < 8; i++)
        #pragma unroll
        for (int j = 0; j < 4; j++) o[i][j] = 0.f;

    for (int kt = 0; kt <= qi; kt++) {
        // ---- 1. S = Q K^T  (3-mma split) ----
        float sacc[4][4];
        #pragma unroll
        for (int i = 0; i < 4; i++)
            #pragma unroll
            for (int j = 0; j < 4; j++) sacc[i][j] = 0.f;

        #pragma unroll 4
        for (int kk = 0; kk < 16; kk++) {
            unsigned ah[4], al[4];
            const int arow0 = (wm + fr) * FQP + kk * 8 + fc;
            const int arow1 = (wm + fr + 8) * FQP + kk * 8 + fc;
            split_tf32(Qs[arow0],     ah[0], al[0]);
            split_tf32(Qs[arow1],     ah[1], al[1]);
            split_tf32(Qs[arow0 + 4], ah[2], al[2]);
            split_tf32(Qs[arow1 + 4], ah[3], al[3]);
            #pragma unroll
            for (int nt = 0; nt < 4; nt++) {
                const int brow = (wh * 32 + nt * 8 + fr) * FKP + kk * 8 + fc;
                unsigned bh[2], bl[2];
                split_tf32(Ks[brow],     bh[0], bl[0]);
                split_tf32(Ks[brow + 4], bh[1], bl[1]);
                mma_tf32(sacc[nt], ah, bh);
                mma_tf32(sacc[nt], ah, bl);
                mma_tf32(sacc[nt], al, bh);
            }
        }
        __syncthreads();   // Ks consumed; prev PV done with Vs

        // ---- 3. store V regs -> Vs, S frags -> Ps (mask), prefetch next K ----
        #pragma unroll
        for (int i = 0; i < 8; i++) {
            float* p = &Vs[g_r * FVP + g_c0 + 4 * i];
            p[0] = vreg[i].x; p[1] = vreg[i].y; p[2] = vreg[i].z; p[3] = vreg[i].w;
        }
        const bool diag = (kt == qi);
        #pragma unroll
        for (int nt = 0; nt < 4; nt++) {
            const int ct = wh * 32 + nt * 8 + 2 * fc;
            const int rt0 = wm + fr, rt1 = wm + fr + 8;
            float s0 = sacc[nt][0], s1 = sacc[nt][1], s2 = sacc[nt][2], s3 = sacc[nt][3];
            if (diag) {
                if (ct     > rt0) s0 = -INFINITY;
                if (ct + 1 > rt0) s1 = -INFINITY;
                if (ct     > rt1) s2 = -INFINITY;
                if (ct + 1 > rt1) s3 = -INFINITY;
            }
            Ps[rt0 * FPP + ct] = s0; Ps[rt0 * FPP + ct + 1] = s1;
            Ps[rt1 * FPP + ct] = s2; Ps[rt1 * FPP + ct + 1] = s3;
        }
        float4 kreg[8];
        if (kt < qi) {
            const float* Kg = g_K + ((size_t)(b * SEQ + (kt + 1) * 64)) * D_MODEL + head_off;
            #pragma unroll
            for (int i = 0; i < 8; i++)
                kreg[i] = *reinterpret_cast<const float4*>(&Kg[(size_t)g_r * D_MODEL + g_c0 + 4 * i]);
        }
        __syncthreads();   // Vs, Ps visible

        // ---- 5. online softmax: 4 threads per row ----
        {
            const int r = tid >> 2;
            const int qq = tid & 3;
            float* prow = &Ps[r * FPP + qq * 16];
            float mx = -INFINITY;
            #pragma unroll
            for (int c = 0; c < 16; c++) mx = fmaxf(mx, prow[c]);
            mx = fmaxf(mx, __shfl_xor_sync(0xffffffffu, mx, 1));
            mx = fmaxf(mx, __shfl_xor_sync(0xffffffffu, mx, 2));
            const float mold = m_s[r];
            const float mnew = fmaxf(mold, mx);
            float sum = 0.f;
            #pragma unroll
            for (int c = 0; c < 16; c++) {
                float p = __expf(prow[c] - mnew);
                prow[c] = p;
                sum += p;
            }
            sum += __shfl_xor_sync(0xffffffffu, sum, 1);
            sum += __shfl_xor_sync(0xffffffffu, sum, 2);
            if (qq == 0) {
                const float alpha = __expf(mold - mnew);
                l_s[r] = l_s[r] * alpha + sum;
                m_s[r] = mnew;
                al_s[r] = alpha;
            }
        }
        __syncthreads();   // P final, alpha ready

        // ---- 7. O = O*alpha + P V (3-mma split); store kreg -> Ks; prefetch V ----
        {
            const float a0 = al_s[wm + fr];
            const float a1 = al_s[wm + fr + 8];
            #pragma unroll
            for (int nt = 0; nt < 8; nt++) {
                o[nt][0] *= a0; o[nt][1] *= a0;
                o[nt][2] *= a1; o[nt][3] *= a1;
            }
        }
        if (kt < qi) {
            #pragma unroll
            for (int i = 0; i < 8; i++) {
                float* p = &Ks[g_r * FKP + g_c0 + 4 * i];
                p[0] = kreg[i].x; p[1] = kreg[i].y; p[2] = kreg[i].z; p[3] = kreg[i].w;
            }
            const float* Vg = g_V + ((size_t)(b * SEQ + (kt + 1) * 64)) * D_MODEL + head_off;
            #pragma unroll
            for (int i = 0; i < 8; i++)
                vreg[i] = *reinterpret_cast<const float4*>(&Vg[(size_t)g_r * D_MODEL + g_c0 + 4 * i]);
        }
        #pragma unroll 2
        for (int ks = 0; ks < 8; ks++) {
            unsigned ph[4], pl[4];
            const int prow0 = (wm + fr) * FPP + ks * 8 + fc;
            const int prow1 = (wm + fr + 8) * FPP + ks * 8 + fc;
            split_tf32(Ps[prow0],     ph[0], pl[0]);
            split_tf32(Ps[prow1],     ph[1], pl[1]);
            split_tf32(Ps[prow0 + 4], ph[2], pl[2]);
            split_tf32(Ps[prow1 + 4], ph[3], pl[3]);
            #pragma unroll
            for (int nt = 0; nt < 8; nt++) {
                const int h0 = wh * 64 + nt * 8 + fr;
                unsigned vh[2], vl[2];
                split_tf32(Vs[(ks * 8 + fc) * FVP + h0],     vh[0], vl[0]);
                split_tf32(Vs[(ks * 8 + fc + 4) * FVP + h0], vh[1], vl[1]);
                mma_tf32(o[nt], ph, vh);
                mma_tf32(o[nt], ph, vl);
                mma_tf32(o[nt], pl, vh);
            }
        }
        __syncthreads();   // Vs/Ps consumed, Ks store visible for next QK
    }

    // ---- epilogue: normalize by l, write to g_A ----
    const float inv0 = 1.f / l_s[wm + fr];
    const float inv1 = 1.f / l_s[wm + fr + 8];
    float* Ab = g_A + ((size_t)(b * SEQ + qi * 64)) * D_MODEL + head_off;
    #pragma unroll
    for (int nt = 0; nt < 8; nt++) {
        const int col = wh * 64 + nt * 8 + 2 * fc;
        const int r0 = wm + fr, r1 = wm + fr + 8;
        *reinterpret_cast<float2*>(&Ab[(size_t)r0 * D_MODEL + col]) =
            make_float2(o[nt][0] * inv0, o[nt][1] * inv0);
        *reinterpret_cast<float2*>(&Ab[(size_t)r1 * D_MODEL + col]) =
            make_float2(o[nt][2] * inv1, o[nt][3] * inv1);
    }
}

// ---------------------------------------------------------------------------
// Decode: zero the q1/k1/v1 accumulators
// ---------------------------------------------------------------------------
__global__ void decode_init_kernel()
{
    const int i = blockIdx.x * 256 + threadIdx.x;
    if (i < BATCH * D_MODEL) {
        g_q1[i] = 0.f; g_k1[i] = 0.f; g_v1[i] = 0.f;
    }
}

// ---------------------------------------------------------------------------
// Decode projections, split-K: grid (D_MODEL/256, BATCH*3, 8), block 256.
// Each block: 256 cols x 256 d-rows partial dot, atomicAdd into output.
// ---------------------------------------------------------------------------
__global__ __launch_bounds__(256) void decode_proj_kernel(
    const float* __restrict__ xnew,
    const float* __restrict__ wq, const float* __restrict__ wk,
    const float* __restrict__ wv)
{
    const int col = blockIdx.x * 256 + threadIdx.x;
    const int b = blockIdx.y & 1;
    const int w = blockIdx.y >> 1;
    const int d0 = blockIdx.z * 256;
    const float* wsel = (w == 0) ? wq : (w == 1) ? wk : wv;
    float* osel = (w == 0) ? g_q1 : (w == 1) ? g_k1 : g_v1;

    __shared__ float xs[256];
    xs[threadIdx.x] = xnew[b * D_MODEL + d0 + threadIdx.x];
    __syncthreads();

    float acc = 0.f;
    #pragma unroll 8
    for (int d = 0; d < 256; d++)
        acc += xs[d] * wsel[(size_t)(d0 + d) * D_MODEL + col];
    atomicAdd(&osel[b * D_MODEL + col], acc);
}

// ---------------------------------------------------------------------------
// Decode attention: per (head, batch), softmax over S+1 = 2049 keys.
// grid = (NHEADS, BATCH), block = 256 (8 warps). Warp-per-key dots.
// ---------------------------------------------------------------------------
__global__ __launch_bounds__(256) void decode_attn_kernel()
{
    const int n = blockIdx.x;
    const int b = blockIdx.y;
    const int tid = threadIdx.x;
    const int lane = tid & 31;
    const int warp = tid >> 5;

    __shared__ float qs[HDIM];
    __shared__ float sc[SEQ + 1];
    __shared__ float red[256];

    if (tid < HDIM) qs[tid] = g_q1[b * D_MODEL + n * HDIM + tid];
    __syncthreads();

    const float scale = 0.08838834764831843f;
    const float4 qv = *reinterpret_cast<const float4*>(&qs[lane * 4]);

    for (int t = warp; t < SEQ + 1; t += 8) {
        const float* kr = (t < SEQ)
            ? (g_K + ((size_t)(b * SEQ + t)) * D_MODEL + n * HDIM)
            : (g_k1 + b * D_MODEL + n * HDIM);
        float4 kv = *reinterpret_cast<const float4*>(&kr[lane * 4]);
        float s = qv.x * kv.x + qv.y * kv.y + qv.z * kv.z + qv.w * kv.w;
        #pragma unroll
        for (int o = 16; o > 0; o >>= 1) s += __shfl_xor_sync(0xffffffffu, s, o);
        if (lane == 0) sc[t] = s * scale;
    }
    __syncthreads();

    // block max
    float mx = -INFINITY;
    for (int t = tid; t < SEQ + 1; t += 256) mx = fmaxf(mx, sc[t]);
    red[tid] = mx;
    __syncthreads();
    for (int s = 128; s > 0; s >>= 1) {
        if (tid < s) red[tid] = fmaxf(red[tid], red[tid + s]);
        __syncthreads();
    }
    mx = red[0];
    __syncthreads();

    // exp + sum
    float sum = 0.f;
    for (int t = tid; t < SEQ + 1; t += 256) {
        float p = __expf(sc[t] - mx);
        sc[t] = p;
        sum += p;
    }
    red[tid] = sum;
    __syncthreads();
    for (int s = 128; s > 0; s >>= 1) {
        if (tid < s) red[tid] += red[tid + s];
        __syncthreads();
    }
    const float inv = 1.f / red[0];
    __syncthreads();

    // V accumulation: 2 t-halves x 128 h channels
    const int h = tid & 127;
    const int half = tid >> 7;
    float acc = 0.f;
    #pragma unroll 4
    for (int t = half; t < SEQ; t += 2)
        acc += sc[t] * g_V[((size_t)(b * SEQ + t)) * D_MODEL + n * HDIM + h];
    if (half == 0) acc += sc[SEQ] * g_v1[b * D_MODEL + n * HDIM + h];
    red[tid] = acc;
    __syncthreads();
    if (tid < 128)
        g_a1[b * D_MODEL + n * HDIM + tid] = (red[tid] + red[tid + 128]) * inv;
}

// ---------------------------------------------------------------------------
// Decode output projection: out[b,d] = sum_k g_a1[b,k] * wo[d,k]
// ---------------------------------------------------------------------------
__global__ __launch_bounds__(256) void decode_out_kernel(
    const float* __restrict__ wo, float* __restrict__ out)
{
    const int gw = (blockIdx.x * 256 + threadIdx.x) >> 5;
    const int lane = threadIdx.x & 31;
    if (gw >= BATCH * D_MODEL) return;
    const int b = gw >> 11;
    const int d = gw & (D_MODEL - 1);

    const float* a = g_a1 + b * D_MODEL;
    const float* w = wo + (size_t)d * D_MODEL;
    float acc = 0.f;
    for (int k = lane * 4; k < D_MODEL; k += 128) {
        float4 av = *reinterpret_cast<const float4*>(a + k);
        float4 wv = *reinterpret_cast<const float4*>(w + k);
        acc += av.x * wv.x + av.y * wv.y + av.z * wv.z + av.w * wv.w;
    }
    #pragma unroll
    for (int o = 16; o > 0; o >>= 1) acc += __shfl_down_sync(0xffffffff, acc, o);
    if (lane == 0) out[PREFILL_ELEMS + b * D_MODEL + d] = acc;
}

// ---------------------------------------------------------------------------
extern "C" void kernel_launch(void* const* d_in, const int* in_sizes, int n_in,
                              void* d_out, int out_size)
{
    const float* x     = (const float*)d_in[0];
    const float* x_new = (const float*)d_in[1];
    const float* wq    = (const float*)d_in[2];
    const float* wk    = (const float*)d_in[3];
    const float* wv    = (const float*)d_in[4];
    const float* wo    = (const float*)d_in[5];
    float* out = (float*)d_out;

    float *pQ, *pK, *pV, *pA;
    cudaGetSymbolAddress((void**)&pQ, g_Q);
    cudaGetSymbolAddress((void**)&pK, g_K);
    cudaGetSymbolAddress((void**)&pV, g_V);
    cudaGetSymbolAddress((void**)&pA, g_A);

    const int flash_smem = FLASH_SMEM_FLOATS * sizeof(float);
    static bool attr_set = false;
    if (!attr_set) {
        cudaFuncSetAttribute(flash_mma_kernel,
                             cudaFuncAttributeMaxDynamicSharedMemorySize, flash_smem);
        attr_set = true;
    }

    // Fused Q/K/V projections on tensor cores (tf32)
    dim3 g3(D_MODEL / 128, MROWS / 128, 3);
    mma_gemm_kernel<false><<<g3, 256>>>(x, wq, wk, wv, pQ, pK, pV,
                                        MROWS, D_MODEL, D_MODEL);

    // Prefill flash attention (tf32 mma, split-corrected)
    dim3 fgrid(SEQ / 64, NHEADS, BATCH);
    flash_mma_kernel<<<fgrid, 256, flash_smem>>>();

    // Output projection (B transposed): prefill_out = A @ wo^T
    dim3 g1(D_MODEL / 128, MROWS / 128, 1);
    mma_gemm_kernel<true><<<g1, 256>>>(pA, wo, wo, wo, out, out, out,
                                       MROWS, D_MODEL, D_MODEL);

    // Decode path
    decode_init_kernel<<<(BATCH * D_MODEL + 255) / 256, 256>>>();
    dim3 dpgrid(D_MODEL / 256, BATCH * 3, 8);
    decode_proj_kernel<<<dpgrid, 256>>>(x_new, wq, wk, wv);
    dim3 dagrid(NHEADS, BATCH);
    decode_attn_kernel<<<dagrid, 256>>>();
    decode_out_kernel<<<512, 256>>>(wo, out);
}

// round 8
// speedup vs baseline: 4.5500x; 1.1536x over previous
#include <cuda_runtime.h>
#include <cuda_fp16.h>
#include <cuda_bf16.h>
#include <math.h>

// ---------------------------------------------------------------------------
// AttentionDisaggregated: prefill (causal self-attn over S=2048) + 1-token decode
// B=2, S=2048, D_MODEL=2048, N_HEADS=16, HEAD_DIM=128
// Round 5: fp16 m16n8k16 HMMA everywhere (tcgen05 unavailable: PTX target is
// compute_103 without the 'a' feature set). Projections = fp16 single pass
// (10-bit mantissa == tf32). Flash = fp16 hi/lo 3-mma split, pre-split smem.
// ---------------------------------------------------------------------------

#define D_MODEL 2048
#define SEQ     2048
#define BATCH   2
#define NHEADS  16
#define HDIM    128
#define MROWS   (BATCH * SEQ)          // 4096
#define PREFILL_ELEMS (BATCH * SEQ * D_MODEL)  // 8388608

// Scratch (device globals -- allocation-free rule)
__device__ float g_Q[MROWS * D_MODEL];
__device__ float g_K[MROWS * D_MODEL];
__device__ float g_V[MROWS * D_MODEL];
__device__ float g_A[MROWS * D_MODEL];
__device__ float g_q1[BATCH * D_MODEL];
__device__ float g_k1[BATCH * D_MODEL];
__device__ float g_v1[BATCH * D_MODEL];
__device__ float g_a1[BATCH * D_MODEL];

// ---------------------------------------------------------------------------
// fp16 mma helper: D(f32) += A(f16) * B(f16), m16n8k16, A row-major, B col-major
// ---------------------------------------------------------------------------
__device__ __forceinline__ void mma_f16(float* c, const unsigned* a, const unsigned* b) {
    asm volatile(
        "mma.sync.aligned.m16n8k16.row.col.f32.f16.f16.f32 "
        "{%0,%1,%2,%3}, {%4,%5,%6,%7}, {%8,%9}, {%0,%1,%2,%3};\n"
        : "+f"(c[0]), "+f"(c[1]), "+f"(c[2]), "+f"(c[3])
        : "r"(a[0]), "r"(a[1]), "r"(a[2]), "r"(a[3]), "r"(b[0]), "r"(b[1]));
}

__device__ __forceinline__ unsigned pack_h2(float x, float y) {
    __half2 h = __halves2half2(__float2half_rn(x), __float2half_rn(y));
    return *reinterpret_cast<unsigned*>(&h);
}

__device__ __forceinline__ void split_pair(float x, float y, unsigned& hi, unsigned& lo) {
    __half hx = __float2half_rn(x), hy = __float2half_rn(y);
    __half lx = __float2half_rn(x - __half2float(hx));
    __half ly = __float2half_rn(y - __half2float(hy));
    __half2 h = __halves2half2(hx, hy), l = __halves2half2(lx, ly);
    hi = *reinterpret_cast<unsigned*>(&h);
    lo = *reinterpret_cast<unsigned*>(&l);
}

// ---------------------------------------------------------------------------
// fp16 HMMA GEMM: C[M,N] = A[M,K] @ B[K,N]   (TRANS_B=false, B gmem [k][n])
//              or C[M,N] = A[M,K] @ B[N,K]^T (TRANS_B=true,  B gmem [n][k])
// BM=BN=128, BK=32, 256 threads, 8 warps each 32x64, double-buffered.
// Bs always stored [n][k] (n rows, k contiguous) so b-frags are half2 loads.
// M,N,K strides hardcoded to 2048.
// ---------------------------------------------------------------------------
#define GSTRIDE 40   // smem row stride in halves (conflict-free: fr*20 mod 32 distinct)

template <bool TRANS_B>
__global__ __launch_bounds__(256, 2) void hgemm_kernel(
    const float* __restrict__ A,
    const float* __restrict__ B0, const float* __restrict__ B1, const float* __restrict__ B2,
    float* __restrict__ C0, float* __restrict__ C1, float* __restrict__ C2)
{
    const float* Bg = (blockIdx.z == 0) ? B0 : (blockIdx.z == 1) ? B1 : B2;
    float*       Cg = (blockIdx.z == 0) ? C0 : (blockIdx.z == 1) ? C1 : C2;

    __shared__ __half As[2][128][GSTRIDE];
    __shared__ __half Bs[2][128][GSTRIDE];

    const int tid  = threadIdx.x;
    const int bm   = blockIdx.y * 128;
    const int bn   = blockIdx.x * 128;
    const int lane = tid & 31;
    const int warp = tid >> 5;
    const int wm   = (warp >> 1) * 32;
    const int wn   = (warp & 1) * 64;
    const int fr   = lane >> 2;
    const int fc   = lane & 3;

    // loader mapping (A and TT-B): 128 rows x 32 k, 16 floats per thread
    const int l_r = tid >> 1;
    const int l_k = (tid & 1) * 16;
    // NN-B loader: k pairs x 8 n
    const int l_kp = (tid & 15) * 2;
    const int l_nb = (tid >> 4) * 8;

    float acc[2][8][4];
    #pragma unroll
    for (int i = 0; i < 2; i++)
        #pragma unroll
        for (int j = 0; j < 8; j++)
            #pragma unroll
            for (int q = 0; q < 4; q++) acc[i][j][q] = 0.f;

    float4 ra[4], rb[4];

    auto issue_loads = [&](int k0) {
        #pragma unroll
        for (int j = 0; j < 4; j++)
            ra[j] = *reinterpret_cast<const float4*>(&A[(size_t)(bm + l_r) * 2048 + k0 + l_k + 4 * j]);
        if (TRANS_B) {
            #pragma unroll
            for (int j = 0; j < 4; j++)
                rb[j] = *reinterpret_cast<const float4*>(&Bg[(size_t)(bn + l_r) * 2048 + k0 + l_k + 4 * j]);
        } else {
            rb[0] = *reinterpret_cast<const float4*>(&Bg[(size_t)(k0 + l_kp) * 2048 + bn + l_nb]);
            rb[1] = *reinterpret_cast<const float4*>(&Bg[(size_t)(k0 + l_kp) * 2048 + bn + l_nb + 4]);
            rb[2] = *reinterpret_cast<const float4*>(&Bg[(size_t)(k0 + l_kp + 1) * 2048 + bn + l_nb]);
            rb[3] = *reinterpret_cast<const float4*>(&Bg[(size_t)(k0 + l_kp + 1) * 2048 + bn + l_nb + 4]);
        }
    };

    auto store_tiles = [&](int sb) {
        #pragma unroll
        for (int j = 0; j < 4; j++) {
            unsigned* p = reinterpret_cast<unsigned*>(&As[sb][l_r][l_k + 4 * j]);
            p[0] = pack_h2(ra[j].x, ra[j].y);
            p[1] = pack_h2(ra[j].z, ra[j].w);
        }
        if (TRANS_B) {
            #pragma unroll
            for (int j = 0; j < 4; j++) {
                unsigned* p = reinterpret_cast<unsigned*>(&Bs[sb][l_r][l_k + 4 * j]);
                p[0] = pack_h2(rb[j].x, rb[j].y);
                p[1] = pack_h2(rb[j].z, rb[j].w);
            }
        } else {
            const float* r0 = reinterpret_cast<const float*>(&rb[0]);  // rb[0],rb[1] = row kp
            const float* r1 = reinterpret_cast<const float*>(&rb[2]);  // rb[2],rb[3] = row kp+1
            #pragma unroll
            for (int i = 0; i < 8; i++)
                *reinterpret_cast<unsigned*>(&Bs[sb][l_nb + i][l_kp]) = pack_h2(r0[i], r1[i]);
        }
    };

    issue_loads(0);
    store_tiles(0);
    __syncthreads();

    int buf = 0;
    for (int k0 = 0; k0 < 2048; k0 += 32) {
        const bool has_next = (k0 + 32) < 2048;
        if (has_next) issue_loads(k0 + 32);

        #pragma unroll
        for (int ks = 0; ks < 2; ks++) {
            const int kk = ks * 16 + 2 * fc;
            unsigned afr[2][4];
            #pragma unroll
            for (int mt = 0; mt < 2; mt++) {
                const int m0 = wm + mt * 16;
                afr[mt][0] = *reinterpret_cast<const unsigned*>(&As[buf][m0 + fr    ][kk]);
                afr[mt][1] = *reinterpret_cast<const unsigned*>(&As[buf][m0 + fr + 8][kk]);
                afr[mt][2] = *reinterpret_cast<const unsigned*>(&As[buf][m0 + fr    ][kk + 8]);
                afr[mt][3] = *reinterpret_cast<const unsigned*>(&As[buf][m0 + fr + 8][kk + 8]);
            }
            #pragma unroll
            for (int nt = 0; nt < 8; nt++) {
                const int n0 = wn + nt * 8 + fr;
                unsigned bfr[2];
                bfr[0] = *reinterpret_cast<const unsigned*>(&Bs[buf][n0][kk]);
                bfr[1] = *reinterpret_cast<const unsigned*>(&Bs[buf][n0][kk + 8]);
                mma_f16(acc[0][nt], afr[0], bfr);
                mma_f16(acc[1][nt], afr[1], bfr);
            }
        }

        if (has_next) store_tiles(buf ^ 1);
        __syncthreads();
        buf ^= 1;
    }

    #pragma unroll
    for (int mt = 0; mt < 2; mt++) {
        #pragma unroll
        for (int nt = 0; nt < 8; nt++) {
            const int row0 = bm + wm + mt * 16 + fr;
            const int col  = bn + wn + nt * 8 + 2 * fc;
            *reinterpret_cast<float2*>(&Cg[(size_t)row0 * 2048 + col]) =
                make_float2(acc[mt][nt][0], acc[mt][nt][1]);
            *reinterpret_cast<float2*>(&Cg[(size_t)(row0 + 8) * 2048 + col]) =
                make_float2(acc[mt][nt][2], acc[mt][nt][3]);
        }
    }
}

// ---------------------------------------------------------------------------
// Flash attention prefill, fp16 hi/lo 3-mma split (near-fp32 accuracy).
// BQ=BK=64, 256 threads (8 warps, warp tile 16 rows x 32/64 cols).
// smem (halves): Qh/Ql [64][136], Kh/Kl [64][136], Vth/Vtl [128][72] (V^T),
// Ps f32 [64][68], Ph/Pl [64][72]. ~140KB dynamic.
// ---------------------------------------------------------------------------
#define FQS 136   // Q/K row stride (halves): 68 words, fr*4 banks -> conflict-free
#define FVS 72    // Vt/P row stride (halves): 36 words, fr*4 banks -> conflict-free
#define FPSF 68   // Ps row stride (floats)

#define OFF_QH  0
#define OFF_QL  (OFF_QH + 64 * FQS * 2)
#define OFF_KH  (OFF_QL + 64 * FQS * 2)
#define OFF_KL  (OFF_KH + 64 * FQS * 2)
#define OFF_VTH (OFF_KL + 64 * FQS * 2)
#define OFF_VTL (OFF_VTH + 128 * FVS * 2)
#define OFF_PS  (OFF_VTL + 128 * FVS * 2)
#define OFF_PH  (OFF_PS + 64 * FPSF * 4)
#define OFF_PL  (OFF_PH + 64 * FVS * 2)
#define OFF_M   (OFF_PL + 64 * FVS * 2)
#define OFF_L   (OFF_M + 64 * 4)
#define OFF_AL  (OFF_L + 64 * 4)
#define FLASH_SMEM_BYTES (OFF_AL + 64 * 4)

__global__ __launch_bounds__(256) void flash_hmma_kernel()
{
    extern __shared__ char fsm[];
    __half* Qh  = reinterpret_cast<__half*>(fsm + OFF_QH);
    __half* Ql  = reinterpret_cast<__half*>(fsm + OFF_QL);
    __half* Kh  = reinterpret_cast<__half*>(fsm + OFF_KH);
    __half* Kl  = reinterpret_cast<__half*>(fsm + OFF_KL);
    __half* Vth = reinterpret_cast<__half*>(fsm + OFF_VTH);
    __half* Vtl = reinterpret_cast<__half*>(fsm + OFF_VTL);
    float*  Ps  = reinterpret_cast<float*>(fsm + OFF_PS);
    __half* Ph  = reinterpret_cast<__half*>(fsm + OFF_PH);
    __half* Pl  = reinterpret_cast<__half*>(fsm + OFF_PL);
    float*  m_s = reinterpret_cast<float*>(fsm + OFF_M);
    float*  l_s = reinterpret_cast<float*>(fsm + OFF_L);
    float*  al_s= reinterpret_cast<float*>(fsm + OFF_AL);

    const int qi = blockIdx.x;
    const int n  = blockIdx.y;
    const int b  = blockIdx.z;
    const int tid  = threadIdx.x;
    const int lane = tid & 31;
    const int warp = tid >> 5;
    const int wm   = (warp >> 1) * 16;
    const int wh   = (warp & 1);
    const int fr   = lane >> 2;
    const int fc   = lane & 3;

    const float scale = 0.08838834764831843f;  // 1/sqrt(128)

    // row-major loader mapping (Q, K): row = tid&63, col base = (tid>>6)*32
    const int g_r  = tid & 63;
    const int g_c0 = (tid >> 6) * 32;
    // V transpose loader: token pair + 16 hdims per thread
    const int v_tp = (lane) * 2;        // within-warp token pair (warp covers all 64 via lane)
    const int v_hb = warp * 16;         // hdim block of 16

    const size_t head_off = (size_t)n * HDIM;

    // ---- load Q (scaled, split hi/lo) ----
    {
        const float* Qg = g_Q + ((size_t)(b * SEQ + qi * 64)) * D_MODEL + head_off;
        #pragma unroll
        for (int i = 0; i < 8; i++) {
            float4 v = *reinterpret_cast<const float4*>(&Qg[(size_t)g_r * D_MODEL + g_c0 + 4 * i]);
            unsigned h0, l0, h1, l1;
            split_pair(v.x * scale, v.y * scale, h0, l0);
            split_pair(v.z * scale, v.w * scale, h1, l1);
            unsigned* ph = reinterpret_cast<unsigned*>(&Qh[g_r * FQS + g_c0 + 4 * i]);
            unsigned* pl = reinterpret_cast<unsigned*>(&Ql[g_r * FQS + g_c0 + 4 * i]);
            ph[0] = h0; ph[1] = h1; pl[0] = l0; pl[1] = l1;
        }
    }
    if (tid < 64) { m_s[tid] = -INFINITY; l_s[tid] = 0.f; }

    // ---- K tile 0 -> smem (split); V tile 0 -> regs ----
    {
        const float* Kg0 = g_K + ((size_t)(b * SEQ)) * D_MODEL + head_off;
        #pragma unroll
        for (int i = 0; i < 8; i++) {
            float4 v = *reinterpret_cast<const float4*>(&Kg0[(size_t)g_r * D_MODEL + g_c0 + 4 * i]);
            unsigned h0, l0, h1, l1;
            split_pair(v.x, v.y, h0, l0);
            split_pair(v.z, v.w, h1, l1);
            unsigned* ph = reinterpret_cast<unsigned*>(&Kh[g_r * FQS + g_c0 + 4 * i]);
            unsigned* pl = reinterpret_cast<unsigned*>(&Kl[g_r * FQS + g_c0 + 4 * i]);
            ph[0] = h0; ph[1] = h1; pl[0] = l0; pl[1] = l1;
        }
    }
    float4 vreg[8];
    {
        const float* Vg0 = g_V + ((size_t)(b * SEQ)) * D_MODEL + head_off;
        #pragma unroll
        for (int j = 0; j < 4; j++) {
            vreg[2*j]   = *reinterpret_cast<const float4*>(&Vg0[(size_t)v_tp * D_MODEL + v_hb + 4 * j]);
            vreg[2*j+1] = *reinterpret_cast<const float4*>(&Vg0[(size_t)(v_tp+1) * D_MODEL + v_hb + 4 * j]);
        }
    }
    __syncthreads();

    float o[8][4];
    #pragma unroll
    for (int i = 0; i < 8; i++)
        #pragma unroll
        for (int j = 0; j < 4; j++) o[i][j] = 0.f;

    for (int kt = 0; kt <= qi; kt++) {
        // ---- 1. S = Q K^T (fp16 3-mma split over HDIM=128 -> 8 k16 chunks) ----
        float sacc[4][4];
        #pragma unroll
        for (int i = 0; i < 4; i++)
            #pragma unroll
            for (int j = 0; j < 4; j++) sacc[i][j] = 0.f;

        #pragma unroll
        for (int kc = 0; kc < 8; kc++) {
            const int kb = kc * 16 + 2 * fc;
            const int ar0 = (wm + fr) * FQS + kb;
            const int ar1 = (wm + fr + 8) * FQS + kb;
            unsigned ah[4], al[4];
            ah[0] = *reinterpret_cast<const unsigned*>(&Qh[ar0]);
            ah[1] = *reinterpret_cast<const unsigned*>(&Qh[ar1]);
            ah[2] = *reinterpret_cast<const unsigned*>(&Qh[ar0 + 8]);
            ah[3] = *reinterpret_cast<const unsigned*>(&Qh[ar1 + 8]);
            al[0] = *reinterpret_cast<const unsigned*>(&Ql[ar0]);
            al[1] = *reinterpret_cast<const unsigned*>(&Ql[ar1]);
            al[2] = *reinterpret_cast<const unsigned*>(&Ql[ar0 + 8]);
            al[3] = *reinterpret_cast<const unsigned*>(&Ql[ar1 + 8]);
            #pragma unroll
            for (int nt = 0; nt < 4; nt++) {
                const int br = (wh * 32 + nt * 8 + fr) * FQS + kb;
                unsigned bh[2], bl[2];
                bh[0] = *reinterpret_cast<const unsigned*>(&Kh[br]);
                bh[1] = *reinterpret_cast<const unsigned*>(&Kh[br + 8]);
                bl[0] = *reinterpret_cast<const unsigned*>(&Kl[br]);
                bl[1] = *reinterpret_cast<const unsigned*>(&Kl[br + 8]);
                mma_f16(sacc[nt], ah, bh);
                mma_f16(sacc[nt], ah, bl);
                mma_f16(sacc[nt], al, bh);
            }
        }
        __syncthreads();   // Kh/Kl consumed; prev PV done with Vt

        // ---- 2. V regs -> Vt smem (transpose+split); S -> Ps (mask); prefetch K ----
        #pragma unroll
        for (int j = 0; j < 4; j++) {
            const float* v0 = reinterpret_cast<const float*>(&vreg[2*j]);
            const float* v1 = reinterpret_cast<const float*>(&vreg[2*j+1]);
            #pragma unroll
            for (int c = 0; c < 4; c++) {
                const int h = v_hb + 4 * j + c;
                unsigned hi, lo;
                split_pair(v0[c], v1[c], hi, lo);
                *reinterpret_cast<unsigned*>(&Vth[h * FVS + v_tp]) = hi;
                *reinterpret_cast<unsigned*>(&Vtl[h * FVS + v_tp]) = lo;
            }
        }
        const bool diag = (kt == qi);
        #pragma unroll
        for (int nt = 0; nt < 4; nt++) {
            const int ct = wh * 32 + nt * 8 + 2 * fc;
            const int rt0 = wm + fr, rt1 = wm + fr + 8;
            float s0 = sacc[nt][0], s1 = sacc[nt][1], s2 = sacc[nt][2], s3 = sacc[nt][3];
            if (diag) {
                if (ct     > rt0) s0 = -INFINITY;
                if (ct + 1 > rt0) s1 = -INFINITY;
                if (ct     > rt1) s2 = -INFINITY;
                if (ct + 1 > rt1) s3 = -INFINITY;
            }
            Ps[rt0 * FPSF + ct] = s0; Ps[rt0 * FPSF + ct + 1] = s1;
            Ps[rt1 * FPSF + ct] = s2; Ps[rt1 * FPSF + ct + 1] = s3;
        }
        float4 kreg[8];
        if (kt < qi) {
            const float* Kg = g_K + ((size_t)(b * SEQ + (kt + 1) * 64)) * D_MODEL + head_off;
            #pragma unroll
            for (int i = 0; i < 8; i++)
                kreg[i] = *reinterpret_cast<const float4*>(&Kg[(size_t)g_r * D_MODEL + g_c0 + 4 * i]);
        }
        __syncthreads();   // Vt, Ps visible

        // ---- 3. online softmax (4 threads per row); write Ph/Pl ----
        {
            const int r = tid >> 2;
            const int qq = tid & 3;
            const float* prow = &Ps[r * FPSF + qq * 16];
            float mx = -INFINITY;
            #pragma unroll
            for (int c = 0; c < 16; c++) mx = fmaxf(mx, prow[c]);
            mx = fmaxf(mx, __shfl_xor_sync(0xffffffffu, mx, 1));
            mx = fmaxf(mx, __shfl_xor_sync(0xffffffffu, mx, 2));
            const float mold = m_s[r];
            const float mnew = fmaxf(mold, mx);
            float sum = 0.f;
            #pragma unroll
            for (int c = 0; c < 16; c += 2) {
                float p0 = __expf(prow[c] - mnew);
                float p1 = __expf(prow[c + 1] - mnew);
                sum += p0 + p1;
                unsigned hi, lo;
                split_pair(p0, p1, hi, lo);
                *reinterpret_cast<unsigned*>(&Ph[r * FVS + qq * 16 + c]) = hi;
                *reinterpret_cast<unsigned*>(&Pl[r * FVS + qq * 16 + c]) = lo;
            }
            sum += __shfl_xor_sync(0xffffffffu, sum, 1);
            sum += __shfl_xor_sync(0xffffffffu, sum, 2);
            if (qq == 0) {
                const float alpha = __expf(mold - mnew);
                l_s[r] = l_s[r] * alpha + sum;
                m_s[r] = mnew;
                al_s[r] = alpha;
            }
        }
        __syncthreads();   // Ph/Pl, alpha ready

        // ---- 4. O = O*alpha + P V (fp16 3-mma split); store kreg; prefetch V ----
        {
            const float a0 = al_s[wm + fr];
            const float a1 = al_s[wm + fr + 8];
            #pragma unroll
            for (int nt = 0; nt < 8; nt++) {
                o[nt][0] *= a0; o[nt][1] *= a0;
                o[nt][2] *= a1; o[nt][3] *= a1;
            }
        }
        if (kt < qi) {
            #pragma unroll
            for (int i = 0; i < 8; i++) {
                unsigned h0, l0, h1, l1;
                split_pair(kreg[i].x, kreg[i].y, h0, l0);
                split_pair(kreg[i].z, kreg[i].w, h1, l1);
                unsigned* ph = reinterpret_cast<unsigned*>(&Kh[g_r * FQS + g_c0 + 4 * i]);
                unsigned* pl = reinterpret_cast<unsigned*>(&Kl[g_r * FQS + g_c0 + 4 * i]);
                ph[0] = h0; ph[1] = h1; pl[0] = l0; pl[1] = l1;
            }
            const float* Vg = g_V + ((size_t)(b * SEQ + (kt + 1) * 64)) * D_MODEL + head_off;
            #pragma unroll
            for (int j = 0; j < 4; j++) {
                vreg[2*j]   = *reinterpret_cast<const float4*>(&Vg[(size_t)v_tp * D_MODEL + v_hb + 4 * j]);
                vreg[2*j+1] = *reinterpret_cast<const float4*>(&Vg[(size_t)(v_tp+1) * D_MODEL + v_hb + 4 * j]);
            }
        }
        #pragma unroll
        for (int ks = 0; ks < 4; ks++) {
            const int kb = ks * 16 + 2 * fc;
            const int ar0 = (wm + fr) * FVS + kb;
            const int ar1 = (wm + fr + 8) * FVS + kb;
            unsigned ah[4], al[4];
            ah[0] = *reinterpret_cast<const unsigned*>(&Ph[ar0]);
            ah[1] = *reinterpret_cast<const unsigned*>(&Ph[ar1]);
            ah[2] = *reinterpret_cast<const unsigned*>(&Ph[ar0 + 8]);
            ah[3] = *reinterpret_cast<const unsigned*>(&Ph[ar1 + 8]);
            al[0] = *reinterpret_cast<const unsigned*>(&Pl[ar0]);
            al[1] = *reinterpret_cast<const unsigned*>(&Pl[ar1]);
            al[2] = *reinterpret_cast<const unsigned*>(&Pl[ar0 + 8]);
            al[3] = *reinterpret_cast<const unsigned*>(&Pl[ar1 + 8]);
            #pragma unroll
            for (int nt = 0; nt < 8; nt++) {
                const int br = (wh * 64 + nt * 8 + fr) * FVS + kb;
                unsigned bh[2], bl[2];
                bh[0] = *reinterpret_cast<const unsigned*>(&Vth[br]);
                bh[1] = *reinterpret_cast<const unsigned*>(&Vth[br + 8]);
                bl[0] = *reinterpret_cast<const unsigned*>(&Vtl[br]);
                bl[1] = *reinterpret_cast<const unsigned*>(&Vtl[br + 8]);
                mma_f16(o[nt], ah, bh);
                mma_f16(o[nt], ah, bl);
                mma_f16(o[nt], al, bh);
            }
        }
        __syncthreads();   // Vt/Ph/Pl consumed; Kh/Kl store visible
    }

    // ---- epilogue: normalize, write g_A ----
    const float inv0 = 1.f / l_s[wm + fr];
    const float inv1 = 1.f / l_s[wm + fr + 8];
    float* Ab = g_A + ((size_t)(b * SEQ + qi * 64)) * D_MODEL + head_off;
    #pragma unroll
    for (int nt = 0; nt < 8; nt++) {
        const int col = wh * 64 + nt * 8 + 2 * fc;
        const int r0 = wm + fr, r1 = wm + fr + 8;
        *reinterpret_cast<float2*>(&Ab[(size_t)r0 * D_MODEL + col]) =
            make_float2(o[nt][0] * inv0, o[nt][1] * inv0);
        *reinterpret_cast<float2*>(&Ab[(size_t)r1 * D_MODEL + col]) =
            make_float2(o[nt][2] * inv1, o[nt][3] * inv1);
    }
}

// ---------------------------------------------------------------------------
// Decode kernels (unchanged from R3)
// ---------------------------------------------------------------------------
__global__ void decode_init_kernel()
{
    const int i = blockIdx.x * 256 + threadIdx.x;
    if (i < BATCH * D_MODEL) {
        g_q1[i] = 0.f; g_k1[i] = 0.f; g_v1[i] = 0.f;
    }
}

__global__ __launch_bounds__(256) void decode_proj_kernel(
    const float* __restrict__ xnew,
    const float* __restrict__ wq, const float* __restrict__ wk,
    const float* __restrict__ wv)
{
    const int col = blockIdx.x * 256 + threadIdx.x;
    const int b = blockIdx.y & 1;
    const int w = blockIdx.y >> 1;
    const int d0 = blockIdx.z * 256;
    const float* wsel = (w == 0) ? wq : (w == 1) ? wk : wv;
    float* osel = (w == 0) ? g_q1 : (w == 1) ? g_k1 : g_v1;

    __shared__ float xs[256];
    xs[threadIdx.x] = xnew[b * D_MODEL + d0 + threadIdx.x];
    __syncthreads();

    float acc = 0.f;
    #pragma unroll 8
    for (int d = 0; d < 256; d++)
        acc += xs[d] * wsel[(size_t)(d0 + d) * D_MODEL + col];
    atomicAdd(&osel[b * D_MODEL + col], acc);
}

__global__ __launch_bounds__(256) void decode_attn_kernel()
{
    const int n = blockIdx.x;
    const int b = blockIdx.y;
    const int tid = threadIdx.x;
    const int lane = tid & 31;
    const int warp = tid >> 5;

    __shared__ float qs[HDIM];
    __shared__ float sc[SEQ + 1];
    __shared__ float red[256];

    if (tid < HDIM) qs[tid] = g_q1[b * D_MODEL + n * HDIM + tid];
    __syncthreads();

    const float scale = 0.08838834764831843f;
    const float4 qv = *reinterpret_cast<const float4*>(&qs[lane * 4]);

    for (int t = warp; t < SEQ + 1; t += 8) {
        const float* kr = (t < SEQ)
            ? (g_K + ((size_t)(b * SEQ + t)) * D_MODEL + n * HDIM)
            : (g_k1 + b * D_MODEL + n * HDIM);
        float4 kv = *reinterpret_cast<const float4*>(&kr[lane * 4]);
        float s = qv.x * kv.x + qv.y * kv.y + qv.z * kv.z + qv.w * kv.w;
        #pragma unroll
        for (int o = 16; o > 0; o >>= 1) s += __shfl_xor_sync(0xffffffffu, s, o);
        if (lane == 0) sc[t] = s * scale;
    }
    __syncthreads();

    float mx = -INFINITY;
    for (int t = tid; t < SEQ + 1; t += 256) mx = fmaxf(mx, sc[t]);
    red[tid] = mx;
    __syncthreads();
    for (int s = 128; s > 0; s >>= 1) {
        if (tid < s) red[tid] = fmaxf(red[tid], red[tid + s]);
        __syncthreads();
    }
    mx = red[0];
    __syncthreads();

    float sum = 0.f;
    for (int t = tid; t < SEQ + 1; t += 256) {
        float p = __expf(sc[t] - mx);
        sc[t] = p;
        sum += p;
    }
    red[tid] = sum;
    __syncthreads();
    for (int s = 128; s > 0; s >>= 1) {
        if (tid < s) red[tid] += red[tid + s];
        __syncthreads();
    }
    const float inv = 1.f / red[0];
    __syncthreads();

    const int h = tid & 127;
    const int half = tid >> 7;
    float acc = 0.f;
    #pragma unroll 4
    for (int t = half; t < SEQ; t += 2)
        acc += sc[t] * g_V[((size_t)(b * SEQ + t)) * D_MODEL + n * HDIM + h];
    if (half == 0) acc += sc[SEQ] * g_v1[b * D_MODEL + n * HDIM + h];
    red[tid] = acc;
    __syncthreads();
    if (tid < 128)
        g_a1[b * D_MODEL + n * HDIM + tid] = (red[tid] + red[tid + 128]) * inv;
}

__global__ __launch_bounds__(256) void decode_out_kernel(
    const float* __restrict__ wo, float* __restrict__ out)
{
    const int gw = (blockIdx.x * 256 + threadIdx.x) >> 5;
    const int lane = threadIdx.x & 31;
    if (gw >= BATCH * D_MODEL) return;
    const int b = gw >> 11;
    const int d = gw & (D_MODEL - 1);

    const float* a = g_a1 + b * D_MODEL;
    const float* w = wo + (size_t)d * D_MODEL;
    float acc = 0.f;
    for (int k = lane * 4; k < D_MODEL; k += 128) {
        float4 av = *reinterpret_cast<const float4*>(a + k);
        float4 wv = *reinterpret_cast<const float4*>(w + k);
        acc += av.x * wv.x + av.y * wv.y + av.z * wv.z + av.w * wv.w;
    }
    #pragma unroll
    for (int o = 16; o > 0; o >>= 1) acc += __shfl_down_sync(0xffffffff, acc, o);
    if (lane == 0) out[PREFILL_ELEMS + b * D_MODEL + d] = acc;
}

// ---------------------------------------------------------------------------
extern "C" void kernel_launch(void* const* d_in, const int* in_sizes, int n_in,
                              void* d_out, int out_size)
{
    const float* x     = (const float*)d_in[0];
    const float* x_new = (const float*)d_in[1];
    const float* wq    = (const float*)d_in[2];
    const float* wk    = (const float*)d_in[3];
    const float* wv    = (const float*)d_in[4];
    const float* wo    = (const float*)d_in[5];
    float* out = (float*)d_out;

    float *pQ, *pK, *pV, *pA;
    cudaGetSymbolAddress((void**)&pQ, g_Q);
    cudaGetSymbolAddress((void**)&pK, g_K);
    cudaGetSymbolAddress((void**)&pV, g_V);
    cudaGetSymbolAddress((void**)&pA, g_A);

    cudaFuncSetAttribute(flash_hmma_kernel,
                         cudaFuncAttributeMaxDynamicSharedMemorySize, FLASH_SMEM_BYTES);

    // 1. Fused Q/K/V projections (fp16 HMMA, B gmem [k][n])
    dim3 gq(D_MODEL / 128, MROWS / 128, 3);
    hgemm_kernel<false><<<gq, 256>>>(x, wq, wk, wv, pQ, pK, pV);

    // 2-3. decode init + projections (independent of flash; puts flash at launch #4)
    decode_init_kernel<<<(BATCH * D_MODEL + 255) / 256, 256>>>();
    dim3 dpgrid(D_MODEL / 256, BATCH * 3, 8);
    decode_proj_kernel<<<dpgrid, 256>>>(x_new, wq, wk, wv);

    // 4. Prefill flash attention (fp16 3-mma split)  <-- profiled slot
    dim3 fgrid(SEQ / 64, NHEADS, BATCH);
    flash_hmma_kernel<<<fgrid, 256, FLASH_SMEM_BYTES>>>();

    // 5. Output projection (fp16 HMMA, B gmem [n][k])
    dim3 go(D_MODEL / 128, MROWS / 128, 1);
    hgemm_kernel<true><<<go, 256>>>(pA, wo, wo, wo, out, out, out);

    // 6-7. decode attention + output projection
    dim3 dagrid(NHEADS, BATCH);
    decode_attn_kernel<<<dagrid, 256>>>();
    decode_out_kernel<<<512, 256>>>(wo, out);
}

// round 9
// speedup vs baseline: 4.8234x; 1.0601x over previous
#include <cuda_runtime.h>
#include <cuda_fp16.h>
#include <cuda_bf16.h>
#include <math.h>

// ---------------------------------------------------------------------------
// AttentionDisaggregated: prefill (causal self-attn over S=2048) + 1-token decode
// B=2, S=2048, D_MODEL=2048, N_HEADS=16, HEAD_DIM=128
// Round 9: flash softmax in registers (no Ps/Ph/Pl smem), partial-O per warp
// token-half, persistent GEMM grids.
// ---------------------------------------------------------------------------

#define D_MODEL 2048
#define SEQ     2048
#define BATCH   2
#define NHEADS  16
#define HDIM    128
#define MROWS   (BATCH * SEQ)          // 4096
#define PREFILL_ELEMS (BATCH * SEQ * D_MODEL)  // 8388608

__device__ float g_Q[MROWS * D_MODEL];
__device__ float g_K[MROWS * D_MODEL];
__device__ float g_V[MROWS * D_MODEL];
__device__ float g_A[MROWS * D_MODEL];
__device__ float g_q1[BATCH * D_MODEL];
__device__ float g_k1[BATCH * D_MODEL];
__device__ float g_v1[BATCH * D_MODEL];
__device__ float g_a1[BATCH * D_MODEL];

// ---------------------------------------------------------------------------
// fp16 mma helper: D(f32) += A(f16) * B(f16), m16n8k16, A row-major, B col-major
// ---------------------------------------------------------------------------
__device__ __forceinline__ void mma_f16(float* c, const unsigned* a, const unsigned* b) {
    asm volatile(
        "mma.sync.aligned.m16n8k16.row.col.f32.f16.f16.f32 "
        "{%0,%1,%2,%3}, {%4,%5,%6,%7}, {%8,%9}, {%0,%1,%2,%3};\n"
        : "+f"(c[0]), "+f"(c[1]), "+f"(c[2]), "+f"(c[3])
        : "r"(a[0]), "r"(a[1]), "r"(a[2]), "r"(a[3]), "r"(b[0]), "r"(b[1]));
}

__device__ __forceinline__ unsigned pack_h2(float x, float y) {
    __half2 h = __halves2half2(__float2half_rn(x), __float2half_rn(y));
    return *reinterpret_cast<unsigned*>(&h);
}

__device__ __forceinline__ void split_pair(float x, float y, unsigned& hi, unsigned& lo) {
    __half hx = __float2half_rn(x), hy = __float2half_rn(y);
    __half lx = __float2half_rn(x - __half2float(hx));
    __half ly = __float2half_rn(y - __half2float(hy));
    __half2 h = __halves2half2(hx, hy), l = __halves2half2(lx, ly);
    hi = *reinterpret_cast<unsigned*>(&h);
    lo = *reinterpret_cast<unsigned*>(&l);
}

// ---------------------------------------------------------------------------
// Persistent fp16 HMMA GEMM: C[M,N] = A @ B (TRANS_B=false, B gmem [k][n])
//                         or C = A @ B^T   (TRANS_B=true,  B gmem [n][k])
// BM=BN=128, BK=32, 256 threads, 8 warps each 32x64, double-buffered.
// Grid = NPERSIST CTAs looping over (z, by, bx) tiles. Strides = 2048.
// ---------------------------------------------------------------------------
#define GSTRIDE 40
#define NPERSIST 296   // 2 CTAs/SM x 148 SMs

template <bool TRANS_B>
__global__ __launch_bounds__(256, 2) void hgemm_kernel(
    const float* __restrict__ A,
    const float* __restrict__ B0, const float* __restrict__ B1, const float* __restrict__ B2,
    float* __restrict__ C0, float* __restrict__ C1, float* __restrict__ C2,
    int ntiles)
{
    __shared__ __half As[2][128][GSTRIDE];
    __shared__ __half Bs[2][128][GSTRIDE];

    const int tid  = threadIdx.x;
    const int lane = tid & 31;
    const int warp = tid >> 5;
    const int wm   = (warp >> 1) * 32;
    const int wn   = (warp & 1) * 64;
    const int fr   = lane >> 2;
    const int fc   = lane & 3;

    const int l_r = tid >> 1;
    const int l_k = (tid & 1) * 16;
    const int l_kp = (tid & 15) * 2;
    const int l_nb = (tid >> 4) * 8;

    for (int t = blockIdx.x; t < ntiles; t += NPERSIST) {
        const int z  = t >> 9;            // /512 tiles per matrix
        const int r  = t & 511;
        const int bm = (r >> 4) * 128;    // 32 row tiles
        const int bn = (r & 15) * 128;    // 16 col tiles

        const float* Bg = (z == 0) ? B0 : (z == 1) ? B1 : B2;
        float*       Cg = (z == 0) ? C0 : (z == 1) ? C1 : C2;

        float acc[2][8][4];
        #pragma unroll
        for (int i = 0; i < 2; i++)
            #pragma unroll
            for (int j = 0; j < 8; j++)
                #pragma unroll
                for (int q = 0; q < 4; q++) acc[i][j][q] = 0.f;

        float4 ra[4], rb[4];

        auto issue_loads = [&](int k0) {
            #pragma unroll
            for (int j = 0; j < 4; j++)
                ra[j] = *reinterpret_cast<const float4*>(&A[(size_t)(bm + l_r) * 2048 + k0 + l_k + 4 * j]);
            if (TRANS_B) {
                #pragma unroll
                for (int j = 0; j < 4; j++)
                    rb[j] = *reinterpret_cast<const float4*>(&Bg[(size_t)(bn + l_r) * 2048 + k0 + l_k + 4 * j]);
            } else {
                rb[0] = *reinterpret_cast<const float4*>(&Bg[(size_t)(k0 + l_kp) * 2048 + bn + l_nb]);
                rb[1] = *reinterpret_cast<const float4*>(&Bg[(size_t)(k0 + l_kp) * 2048 + bn + l_nb + 4]);
                rb[2] = *reinterpret_cast<const float4*>(&Bg[(size_t)(k0 + l_kp + 1) * 2048 + bn + l_nb]);
                rb[3] = *reinterpret_cast<const float4*>(&Bg[(size_t)(k0 + l_kp + 1) * 2048 + bn + l_nb + 4]);
            }
        };

        auto store_tiles = [&](int sb) {
            #pragma unroll
            for (int j = 0; j < 4; j++) {
                unsigned* p = reinterpret_cast<unsigned*>(&As[sb][l_r][l_k + 4 * j]);
                p[0] = pack_h2(ra[j].x, ra[j].y);
                p[1] = pack_h2(ra[j].z, ra[j].w);
            }
            if (TRANS_B) {
                #pragma unroll
                for (int j = 0; j < 4; j++) {
                    unsigned* p = reinterpret_cast<unsigned*>(&Bs[sb][l_r][l_k + 4 * j]);
                    p[0] = pack_h2(rb[j].x, rb[j].y);
                    p[1] = pack_h2(rb[j].z, rb[j].w);
                }
            } else {
                const float* r0 = reinterpret_cast<const float*>(&rb[0]);
                const float* r1 = reinterpret_cast<const float*>(&rb[2]);
                #pragma unroll
                for (int i = 0; i < 8; i++)
                    *reinterpret_cast<unsigned*>(&Bs[sb][l_nb + i][l_kp]) = pack_h2(r0[i], r1[i]);
            }
        };

        issue_loads(0);
        store_tiles(0);
        __syncthreads();

        int buf = 0;
        for (int k0 = 0; k0 < 2048; k0 += 32) {
            const bool has_next = (k0 + 32) < 2048;
            if (has_next) issue_loads(k0 + 32);

            #pragma unroll
            for (int ks = 0; ks < 2; ks++) {
                const int kk = ks * 16 + 2 * fc;
                unsigned afr[2][4];
                #pragma unroll
                for (int mt = 0; mt < 2; mt++) {
                    const int m0 = wm + mt * 16;
                    afr[mt][0] = *reinterpret_cast<const unsigned*>(&As[buf][m0 + fr    ][kk]);
                    afr[mt][1] = *reinterpret_cast<const unsigned*>(&As[buf][m0 + fr + 8][kk]);
                    afr[mt][2] = *reinterpret_cast<const unsigned*>(&As[buf][m0 + fr    ][kk + 8]);
                    afr[mt][3] = *reinterpret_cast<const unsigned*>(&As[buf][m0 + fr + 8][kk + 8]);
                }
                #pragma unroll
                for (int nt = 0; nt < 8; nt++) {
                    const int n0 = wn + nt * 8 + fr;
                    unsigned bfr[2];
                    bfr[0] = *reinterpret_cast<const unsigned*>(&Bs[buf][n0][kk]);
                    bfr[1] = *reinterpret_cast<const unsigned*>(&Bs[buf][n0][kk + 8]);
                    mma_f16(acc[0][nt], afr[0], bfr);
                    mma_f16(acc[1][nt], afr[1], bfr);
                }
            }

            if (has_next) store_tiles(buf ^ 1);
            __syncthreads();
            buf ^= 1;
        }

        #pragma unroll
        for (int mt = 0; mt < 2; mt++) {
            #pragma unroll
            for (int nt = 0; nt < 8; nt++) {
                const int row0 = bm + wm + mt * 16 + fr;
                const int col  = bn + wn + nt * 8 + 2 * fc;
                *reinterpret_cast<float2*>(&Cg[(size_t)row0 * 2048 + col]) =
                    make_float2(acc[mt][nt][0], acc[mt][nt][1]);
                *reinterpret_cast<float2*>(&Cg[(size_t)(row0 + 8) * 2048 + col]) =
                    make_float2(acc[mt][nt][2], acc[mt][nt][3]);
            }
        }
    }
}

// ---------------------------------------------------------------------------
// Flash attention prefill, fp16 hi/lo 3-mma split, register softmax.
// BQ=BK=64, 256 threads (8 warps; pair (2w,2w+1) shares 16 Q rows, splits
// the 64 tokens; each warp computes partial O over full hdim=128).
// ---------------------------------------------------------------------------
#define FQS 136   // Q/K row stride (halves)
#define FVS 72    // Vt row stride (halves)

#define OFF_QH  0
#define OFF_QL  (OFF_QH + 64 * FQS * 2)      // 17408
#define OFF_KH  (OFF_QL + 64 * FQS * 2)      // 34816
#define OFF_KL  (OFF_KH + 64 * FQS * 2)      // 52224
#define OFF_VTH (OFF_KL + 64 * FQS * 2)      // 69632
#define OFF_VTL (OFF_VTH + 128 * FVS * 2)    // 88064
#define OFF_PM  (OFF_VTL + 128 * FVS * 2)    // 106496
#define OFF_PSUM (OFF_PM + 128 * 4)          // 107008
#define OFF_M   (OFF_PSUM + 128 * 4)         // 107520
#define OFF_L   (OFF_M + 64 * 4)             // 107776
#define FLASH_SMEM_BYTES (OFF_L + 64 * 4)    // 108032

__global__ __launch_bounds__(256) void flash_hmma_kernel()
{
    extern __shared__ char fsm[];
    __half* Qh  = reinterpret_cast<__half*>(fsm + OFF_QH);
    __half* Ql  = reinterpret_cast<__half*>(fsm + OFF_QL);
    __half* Kh  = reinterpret_cast<__half*>(fsm + OFF_KH);
    __half* Kl  = reinterpret_cast<__half*>(fsm + OFF_KL);
    __half* Vth = reinterpret_cast<__half*>(fsm + OFF_VTH);
    __half* Vtl = reinterpret_cast<__half*>(fsm + OFF_VTL);
    float*  pm   = reinterpret_cast<float*>(fsm + OFF_PM);
    float*  psum = reinterpret_cast<float*>(fsm + OFF_PSUM);
    float*  m_s  = reinterpret_cast<float*>(fsm + OFF_M);
    float*  l_s  = reinterpret_cast<float*>(fsm + OFF_L);

    const int qi = blockIdx.x;
    const int n  = blockIdx.y;
    const int b  = blockIdx.z;
    const int tid  = threadIdx.x;
    const int lane = tid & 31;
    const int warp = tid >> 5;
    const int wm   = (warp >> 1) * 16;   // Q row block (shared by warp pair)
    const int wh   = (warp & 1);         // token-half selector
    const int fr   = lane >> 2;
    const int fc   = lane & 3;

    const float scale = 0.08838834764831843f;  // 1/sqrt(128)

    const int g_r  = tid & 63;
    const int g_c0 = (tid >> 6) * 32;
    const int v_tp = lane * 2;
    const int v_hb = warp * 16;

    const size_t head_off = (size_t)n * HDIM;
    const int r0 = wm + fr, r1 = wm + fr + 8;

    // ---- load Q (scaled, split hi/lo) ----
    {
        const float* Qg = g_Q + ((size_t)(b * SEQ + qi * 64)) * D_MODEL + head_off;
        #pragma unroll
        for (int i = 0; i < 8; i++) {
            float4 v = *reinterpret_cast<const float4*>(&Qg[(size_t)g_r * D_MODEL + g_c0 + 4 * i]);
            unsigned h0, l0, h1, l1;
            split_pair(v.x * scale, v.y * scale, h0, l0);
            split_pair(v.z * scale, v.w * scale, h1, l1);
            unsigned* ph = reinterpret_cast<unsigned*>(&Qh[g_r * FQS + g_c0 + 4 * i]);
            unsigned* pl = reinterpret_cast<unsigned*>(&Ql[g_r * FQS + g_c0 + 4 * i]);
            ph[0] = h0; ph[1] = h1; pl[0] = l0; pl[1] = l1;
        }
    }
    if (tid < 64) { m_s[tid] = -INFINITY; l_s[tid] = 0.f; }

    // ---- K tile 0 -> smem (split); V tile 0 -> regs ----
    {
        const float* Kg0 = g_K + ((size_t)(b * SEQ)) * D_MODEL + head_off;
        #pragma unroll
        for (int i = 0; i < 8; i++) {
            float4 v = *reinterpret_cast<const float4*>(&Kg0[(size_t)g_r * D_MODEL + g_c0 + 4 * i]);
            unsigned h0, l0, h1, l1;
            split_pair(v.x, v.y, h0, l0);
            split_pair(v.z, v.w, h1, l1);
            unsigned* ph = reinterpret_cast<unsigned*>(&Kh[g_r * FQS + g_c0 + 4 * i]);
            unsigned* pl = reinterpret_cast<unsigned*>(&Kl[g_r * FQS + g_c0 + 4 * i]);
            ph[0] = h0; ph[1] = h1; pl[0] = l0; pl[1] = l1;
        }
    }
    float4 vreg[8];
    {
        const float* Vg0 = g_V + ((size_t)(b * SEQ)) * D_MODEL + head_off;
        #pragma unroll
        for (int j = 0; j < 4; j++) {
            vreg[2*j]   = *reinterpret_cast<const float4*>(&Vg0[(size_t)v_tp * D_MODEL + v_hb + 4 * j]);
            vreg[2*j+1] = *reinterpret_cast<const float4*>(&Vg0[(size_t)(v_tp+1) * D_MODEL + v_hb + 4 * j]);
        }
    }
    __syncthreads();

    // partial O over full hdim (128 = 16 n-tiles), this warp's token half only
    float o[16][4];
    #pragma unroll
    for (int i = 0; i < 16; i++)
        #pragma unroll
        for (int j = 0; j < 4; j++) o[i][j] = 0.f;

    for (int kt = 0; kt <= qi; kt++) {
        // ---- 1. S = Q K^T over own 32 cols (fp16 3-mma split) ----
        float sacc[4][4];
        #pragma unroll
        for (int i = 0; i < 4; i++)
            #pragma unroll
            for (int j = 0; j < 4; j++) sacc[i][j] = 0.f;

        #pragma unroll
        for (int kc = 0; kc < 8; kc++) {
            const int kb = kc * 16 + 2 * fc;
            const int ar0 = r0 * FQS + kb;
            const int ar1 = r1 * FQS + kb;
            unsigned ah[4], al[4];
            ah[0] = *reinterpret_cast<const unsigned*>(&Qh[ar0]);
            ah[1] = *reinterpret_cast<const unsigned*>(&Qh[ar1]);
            ah[2] = *reinterpret_cast<const unsigned*>(&Qh[ar0 + 8]);
            ah[3] = *reinterpret_cast<const unsigned*>(&Qh[ar1 + 8]);
            al[0] = *reinterpret_cast<const unsigned*>(&Ql[ar0]);
            al[1] = *reinterpret_cast<const unsigned*>(&Ql[ar1]);
            al[2] = *reinterpret_cast<const unsigned*>(&Ql[ar0 + 8]);
            al[3] = *reinterpret_cast<const unsigned*>(&Ql[ar1 + 8]);
            #pragma unroll
            for (int nt = 0; nt < 4; nt++) {
                const int br = (wh * 32 + nt * 8 + fr) * FQS + kb;
                unsigned bh[2], bl[2];
                bh[0] = *reinterpret_cast<const unsigned*>(&Kh[br]);
                bh[1] = *reinterpret_cast<const unsigned*>(&Kh[br + 8]);
                bl[0] = *reinterpret_cast<const unsigned*>(&Kl[br]);
                bl[1] = *reinterpret_cast<const unsigned*>(&Kl[br + 8]);
                mma_f16(sacc[nt], ah, bh);
                mma_f16(sacc[nt], ah, bl);
                mma_f16(sacc[nt], al, bh);
            }
        }

        // ---- mask (regs) + local row max + quad reduce ----
        if (kt == qi) {
            #pragma unroll
            for (int nt = 0; nt < 4; nt++) {
                const int ct = wh * 32 + nt * 8 + 2 * fc;
                if (ct     > r0) sacc[nt][0] = -INFINITY;
                if (ct + 1 > r0) sacc[nt][1] = -INFINITY;
                if (ct     > r1) sacc[nt][2] = -INFINITY;
                if (ct + 1 > r1) sacc[nt][3] = -INFINITY;
            }
        }
        float mx0 = -INFINITY, mx1 = -INFINITY;
        #pragma unroll
        for (int nt = 0; nt < 4; nt++) {
            mx0 = fmaxf(mx0, fmaxf(sacc[nt][0], sacc[nt][1]));
            mx1 = fmaxf(mx1, fmaxf(sacc[nt][2], sacc[nt][3]));
        }
        mx0 = fmaxf(mx0, __shfl_xor_sync(0xffffffffu, mx0, 1));
        mx0 = fmaxf(mx0, __shfl_xor_sync(0xffffffffu, mx0, 2));
        mx1 = fmaxf(mx1, __shfl_xor_sync(0xffffffffu, mx1, 1));
        mx1 = fmaxf(mx1, __shfl_xor_sync(0xffffffffu, mx1, 2));
        __syncthreads();   // prev PV done with Vt; Kh/Kl consumed

        // ---- 2. V regs -> Vt smem; pm write; prefetch next K ----
        #pragma unroll
        for (int j = 0; j < 4; j++) {
            const float* v0 = reinterpret_cast<const float*>(&vreg[2*j]);
            const float* v1 = reinterpret_cast<const float*>(&vreg[2*j+1]);
            #pragma unroll
            for (int c = 0; c < 4; c++) {
                const int h = v_hb + 4 * j + c;
                unsigned hi, lo;
                split_pair(v0[c], v1[c], hi, lo);
                *reinterpret_cast<unsigned*>(&Vth[h * FVS + v_tp]) = hi;
                *reinterpret_cast<unsigned*>(&Vtl[h * FVS + v_tp]) = lo;
            }
        }
        if (fc == 0) { pm[wh * 64 + r0] = mx0; pm[wh * 64 + r1] = mx1; }
        float4 kreg[8];
        if (kt < qi) {
            const float* Kg = g_K + ((size_t)(b * SEQ + (kt + 1) * 64)) * D_MODEL + head_off;
            #pragma unroll
            for (int i = 0; i < 8; i++)
                kreg[i] = *reinterpret_cast<const float4*>(&Kg[(size_t)g_r * D_MODEL + g_c0 + 4 * i]);
        }
        __syncthreads();   // Vt, pm visible

        // ---- 3. softmax in regs: mnew, alpha, exp, pack P fragments, sums ----
        const float mold0 = m_s[r0], mold1 = m_s[r1];
        const float mn0 = fmaxf(mold0, fmaxf(pm[r0], pm[64 + r0]));
        const float mn1 = fmaxf(mold1, fmaxf(pm[r1], pm[64 + r1]));
        const float alpha0 = __expf(mold0 - mn0);
        const float alpha1 = __expf(mold1 - mn1);

        unsigned Pfh[2][4], Pfl[2][4];
        float s0 = 0.f, s1 = 0.f;
        #pragma unroll
        for (int j = 0; j < 2; j++) {
            float e00 = __expf(sacc[2*j][0] - mn0),   e01 = __expf(sacc[2*j][1] - mn0);
            float e02 = __expf(sacc[2*j][2] - mn1),   e03 = __expf(sacc[2*j][3] - mn1);
            float e10 = __expf(sacc[2*j+1][0] - mn0), e11 = __expf(sacc[2*j+1][1] - mn0);
            float e12 = __expf(sacc[2*j+1][2] - mn1), e13 = __expf(sacc[2*j+1][3] - mn1);
            s0 += e00 + e01 + e10 + e11;
            s1 += e02 + e03 + e12 + e13;
            split_pair(e00, e01, Pfh[j][0], Pfl[j][0]);
            split_pair(e02, e03, Pfh[j][1], Pfl[j][1]);
            split_pair(e10, e11, Pfh[j][2], Pfl[j][2]);
            split_pair(e12, e13, Pfh[j][3], Pfl[j][3]);
        }
        s0 += __shfl_xor_sync(0xffffffffu, s0, 1);
        s0 += __shfl_xor_sync(0xffffffffu, s0, 2);
        s1 += __shfl_xor_sync(0xffffffffu, s1, 1);
        s1 += __shfl_xor_sync(0xffffffffu, s1, 2);
        if (fc == 0) { psum[wh * 64 + r0] = s0; psum[wh * 64 + r1] = s1; }
        __syncthreads();   // psum visible

        // ---- 4. l/m update; O*=alpha; PV (own P regs x Vt smem); K store; V LDG ----
        if (wh == 0 && fc == 0) {
            l_s[r0] = l_s[r0] * alpha0 + psum[r0] + psum[64 + r0];
            l_s[r1] = l_s[r1] * alpha1 + psum[r1] + psum[64 + r1];
            m_s[r0] = mn0;
            m_s[r1] = mn1;
        }
        #pragma unroll
        for (int nt = 0; nt < 16; nt++) {
            o[nt][0] *= alpha0; o[nt][1] *= alpha0;
            o[nt][2] *= alpha1; o[nt][3] *= alpha1;
        }
        if (kt < qi) {
            #pragma unroll
            for (int i = 0; i < 8; i++) {
                unsigned h0, l0, h1, l1;
                split_pair(kreg[i].x, kreg[i].y, h0, l0);
                split_pair(kreg[i].z, kreg[i].w, h1, l1);
                unsigned* ph = reinterpret_cast<unsigned*>(&Kh[g_r * FQS + g_c0 + 4 * i]);
                unsigned* pl = reinterpret_cast<unsigned*>(&Kl[g_r * FQS + g_c0 + 4 * i]);
                ph[0] = h0; ph[1] = h1; pl[0] = l0; pl[1] = l1;
            }
            const float* Vg = g_V + ((size_t)(b * SEQ + (kt + 1) * 64)) * D_MODEL + head_off;
            #pragma unroll
            for (int j = 0; j < 4; j++) {
                vreg[2*j]   = *reinterpret_cast<const float4*>(&Vg[(size_t)v_tp * D_MODEL + v_hb + 4 * j]);
                vreg[2*j+1] = *reinterpret_cast<const float4*>(&Vg[(size_t)(v_tp+1) * D_MODEL + v_hb + 4 * j]);
            }
        }
        #pragma unroll
        for (int j = 0; j < 2; j++) {
            const int w = wh * 2 + j;       // global 16-token window
            #pragma unroll
            for (int nt = 0; nt < 16; nt++) {
                const int br = (nt * 8 + fr) * FVS + w * 16 + 2 * fc;
                unsigned bh[2], bl[2];
                bh[0] = *reinterpret_cast<const unsigned*>(&Vth[br]);
                bh[1] = *reinterpret_cast<const unsigned*>(&Vth[br + 8]);
                bl[0] = *reinterpret_cast<const unsigned*>(&Vtl[br]);
                bl[1] = *reinterpret_cast<const unsigned*>(&Vtl[br + 8]);
                mma_f16(o[nt], Pfh[j], bh);
                mma_f16(o[nt], Pfh[j], bl);
                mma_f16(o[nt], Pfl[j], bh);
            }
        }
        __syncthreads();   // K store visible; Vt consumed
    }

    // ---- epilogue: merge partial O across warp pairs, normalize, store ----
    float* Omrg = reinterpret_cast<float*>(fsm + OFF_KH);   // 32KB scratch (Kh+Kl)
    if (wh == 1) {
        float* dst = &Omrg[((warp >> 1) * 32 + lane) * 64];
        #pragma unroll
        for (int nt = 0; nt < 16; nt++) {
            float4 v = make_float4(o[nt][0], o[nt][1], o[nt][2], o[nt][3]);
            *reinterpret_cast<float4*>(dst + nt * 4) = v;
        }
    }
    __syncthreads();
    if (wh == 0) {
        const float inv0 = 1.f / l_s[r0];
        const float inv1 = 1.f / l_s[r1];
        const float* src = &Omrg[((warp >> 1) * 32 + lane) * 64];
        float* Ab = g_A + ((size_t)(b * SEQ + qi * 64)) * D_MODEL + head_off;
        #pragma unroll
        for (int nt = 0; nt < 16; nt++) {
            float4 v = *reinterpret_cast<const float4*>(src + nt * 4);
            const int col = nt * 8 + 2 * fc;
            *reinterpret_cast<float2*>(&Ab[(size_t)r0 * D_MODEL + col]) =
                make_float2((o[nt][0] + v.x) * inv0, (o[nt][1] + v.y) * inv0);
            *reinterpret_cast<float2*>(&Ab[(size_t)r1 * D_MODEL + col]) =
                make_float2((o[nt][2] + v.z) * inv1, (o[nt][3] + v.w) * inv1);
        }
    }
}

// ---------------------------------------------------------------------------
// Decode kernels (unchanged)
// ---------------------------------------------------------------------------
__global__ void decode_init_kernel()
{
    const int i = blockIdx.x * 256 + threadIdx.x;
    if (i < BATCH * D_MODEL) {
        g_q1[i] = 0.f; g_k1[i] = 0.f; g_v1[i] = 0.f;
    }
}

__global__ __launch_bounds__(256) void decode_proj_kernel(
    const float* __restrict__ xnew,
    const float* __restrict__ wq, const float* __restrict__ wk,
    const float* __restrict__ wv)
{
    const int col = blockIdx.x * 256 + threadIdx.x;
    const int b = blockIdx.y & 1;
    const int w = blockIdx.y >> 1;
    const int d0 = blockIdx.z * 256;
    const float* wsel = (w == 0) ? wq : (w == 1) ? wk : wv;
    float* osel = (w == 0) ? g_q1 : (w == 1) ? g_k1 : g_v1;

    __shared__ float xs[256];
    xs[threadIdx.x] = xnew[b * D_MODEL + d0 + threadIdx.x];
    __syncthreads();

    float acc = 0.f;
    #pragma unroll 8
    for (int d = 0; d < 256; d++)
        acc += xs[d] * wsel[(size_t)(d0 + d) * D_MODEL + col];
    atomicAdd(&osel[b * D_MODEL + col], acc);
}

__global__ __launch_bounds__(256) void decode_attn_kernel()
{
    const int n = blockIdx.x;
    const int b = blockIdx.y;
    const int tid = threadIdx.x;
    const int lane = tid & 31;
    const int warp = tid >> 5;

    __shared__ float qs[HDIM];
    __shared__ float sc[SEQ + 1];
    __shared__ float red[256];

    if (tid < HDIM) qs[tid] = g_q1[b * D_MODEL + n * HDIM + tid];
    __syncthreads();

    const float scale = 0.08838834764831843f;
    const float4 qv = *reinterpret_cast<const float4*>(&qs[lane * 4]);

    for (int t = warp; t < SEQ + 1; t += 8) {
        const float* kr = (t < SEQ)
            ? (g_K + ((size_t)(b * SEQ + t)) * D_MODEL + n * HDIM)
            : (g_k1 + b * D_MODEL + n * HDIM);
        float4 kv = *reinterpret_cast<const float4*>(&kr[lane * 4]);
        float s = qv.x * kv.x + qv.y * kv.y + qv.z * kv.z + qv.w * kv.w;
        #pragma unroll
        for (int o = 16; o > 0; o >>= 1) s += __shfl_xor_sync(0xffffffffu, s, o);
        if (lane == 0) sc[t] = s * scale;
    }
    __syncthreads();

    float mx = -INFINITY;
    for (int t = tid; t < SEQ + 1; t += 256) mx = fmaxf(mx, sc[t]);
    red[tid] = mx;
    __syncthreads();
    for (int s = 128; s > 0; s >>= 1) {
        if (tid < s) red[tid] = fmaxf(red[tid], red[tid + s]);
        __syncthreads();
    }
    mx = red[0];
    __syncthreads();

    float sum = 0.f;
    for (int t = tid; t < SEQ + 1; t += 256) {
        float p = __expf(sc[t] - mx);
        sc[t] = p;
        sum += p;
    }
    red[tid] = sum;
    __syncthreads();
    for (int s = 128; s > 0; s >>= 1) {
        if (tid < s) red[tid] += red[tid + s];
        __syncthreads();
    }
    const float inv = 1.f / red[0];
    __syncthreads();

    const int h = tid & 127;
    const int half = tid >> 7;
    float acc = 0.f;
    #pragma unroll 4
    for (int t = half; t < SEQ; t += 2)
        acc += sc[t] * g_V[((size_t)(b * SEQ + t)) * D_MODEL + n * HDIM + h];
    if (half == 0) acc += sc[SEQ] * g_v1[b * D_MODEL + n * HDIM + h];
    red[tid] = acc;
    __syncthreads();
    if (tid < 128)
        g_a1[b * D_MODEL + n * HDIM + tid] = (red[tid] + red[tid + 128]) * inv;
}

__global__ __launch_bounds__(256) void decode_out_kernel(
    const float* __restrict__ wo, float* __restrict__ out)
{
    const int gw = (blockIdx.x * 256 + threadIdx.x) >> 5;
    const int lane = threadIdx.x & 31;
    if (gw >= BATCH * D_MODEL) return;
    const int b = gw >> 11;
    const int d = gw & (D_MODEL - 1);

    const float* a = g_a1 + b * D_MODEL;
    const float* w = wo + (size_t)d * D_MODEL;
    float acc = 0.f;
    for (int k = lane * 4; k < D_MODEL; k += 128) {
        float4 av = *reinterpret_cast<const float4*>(a + k);
        float4 wv = *reinterpret_cast<const float4*>(w + k);
        acc += av.x * wv.x + av.y * wv.y + av.z * wv.z + av.w * wv.w;
    }
    #pragma unroll
    for (int o = 16; o > 0; o >>= 1) acc += __shfl_down_sync(0xffffffff, acc, o);
    if (lane == 0) out[PREFILL_ELEMS + b * D_MODEL + d] = acc;
}

// ---------------------------------------------------------------------------
extern "C" void kernel_launch(void* const* d_in, const int* in_sizes, int n_in,
                              void* d_out, int out_size)
{
    const float* x     = (const float*)d_in[0];
    const float* x_new = (const float*)d_in[1];
    const float* wq    = (const float*)d_in[2];
    const float* wk    = (const float*)d_in[3];
    const float* wv    = (const float*)d_in[4];
    const float* wo    = (const float*)d_in[5];
    float* out = (float*)d_out;

    float *pQ, *pK, *pV, *pA;
    cudaGetSymbolAddress((void**)&pQ, g_Q);
    cudaGetSymbolAddress((void**)&pK, g_K);
    cudaGetSymbolAddress((void**)&pV, g_V);
    cudaGetSymbolAddress((void**)&pA, g_A);

    cudaFuncSetAttribute(flash_hmma_kernel,
                         cudaFuncAttributeMaxDynamicSharedMemorySize, FLASH_SMEM_BYTES);

    // 1. Fused Q/K/V projections (persistent fp16 HMMA): 1536 tiles
    hgemm_kernel<false><<<NPERSIST, 256>>>(x, wq, wk, wv, pQ, pK, pV, 1536);

    // 2-3. decode init + projections
    decode_init_kernel<<<(BATCH * D_MODEL + 255) / 256, 256>>>();
    dim3 dpgrid(D_MODEL / 256, BATCH * 3, 8);
    decode_proj_kernel<<<dpgrid, 256>>>(x_new, wq, wk, wv);

    // 4. Prefill flash attention (register softmax)  <-- profiled slot
    dim3 fgrid(SEQ / 64, NHEADS, BATCH);
    flash_hmma_kernel<<<fgrid, 256, FLASH_SMEM_BYTES>>>();

    // 5. Output projection (persistent fp16 HMMA): 512 tiles
    hgemm_kernel<true><<<NPERSIST, 256>>>(pA, wo, wo, wo, out, out, out, 512);

    // 6-7. decode attention + output projection
    dim3 dagrid(NHEADS, BATCH);
    decode_attn_kernel<<<dagrid, 256>>>();
    decode_out_kernel<<<512, 256>>>(wo, out);
}